// round 14
// baseline (speedup 1.0000x reference)
#include <cuda_runtime.h>
#include <cuda_bf16.h>
#include <cstdint>

#define NN   8192
#define NE   131072
#define NB   256
#define NHF  128
#define FIN  64
#define H3   384
#define D6   768
#define D12  1536
#define G4   3072
#define SMAXSEG 512
#define KSPLIT 2304
#define NCH2  72          // K-chunks of 32 over 2304

// ---------------- scratch ----------------
__device__ __align__(16) float g_h[2][NN * H3];
__device__ __align__(16) float g_x[2][NN * D6];
__device__ __align__(16) float g_xw[2][NN * NHF];
__device__ float g_deg[2][NN];
__device__ int   g_cnt[2][NN];
__device__ int   g_cursor[2][NN];
__device__ int   g_rowptr[2][NN + 1];
__device__ int   g_csrc[2][NE];
__device__ float g_cnrm[2][NE];
__device__ float g_dinv[2][NN];
__device__ int   g_starts[2][NB + 1];
__device__ float g_cvec[G4];
__device__ __align__(16) float g_rb[2][NB * D6];
__device__ __align__(16) float g_gates[2][NB * G4];
__device__ __align__(16) float g_z[NB * G4];
__device__ __align__(16) float g_z1pre[NB * 256];
__device__ __align__(16) uint32_t g_Bbuf[G4 * (KSPLIT / 2)];   // bf16x2, [3072][1152]: hi|hi|lo

__device__ __forceinline__ float wredsum(float v) {
#pragma unroll
    for (int o = 16; o; o >>= 1) v += __shfl_xor_sync(0xffffffffu, v, o);
    return v;
}
__device__ __forceinline__ float sgm(float x) { return 1.f / (1.f + expf(-x)); }

// ---------------- CSR build (R8 proven) ----------------
__global__ void k_prep() {
    int i = blockIdx.x * blockDim.x + threadIdx.x;
    if (i < 2 * NN) {
        int g = i >> 13, n = i & (NN - 1);
        g_cnt[g][n] = 0;
        g_deg[g][n] = 0.f;
    }
}
__global__ void k_count(const int* __restrict__ ei1, const float* __restrict__ ew1,
                        const int* __restrict__ ei2, const float* __restrict__ ew2) {
    int g = blockIdx.y;
    const int* ei = g ? ei2 : ei1;
    const float* ew = g ? ew2 : ew1;
    int e = blockIdx.x * blockDim.x + threadIdx.x;
    if (e < NE) {
        int d = ei[NE + e];
        atomicAdd(&g_cnt[g][d], 1);
        atomicAdd(&g_deg[g][d], ew[e]);
    }
}
__global__ void k_scan() {
    __shared__ int wsum[32];
    int g = blockIdx.x;
    int t = threadIdx.x, lane = t & 31, w = t >> 5;
    int base = t * 8;
    int loc[8], s = 0;
#pragma unroll
    for (int i = 0; i < 8; i++) { loc[i] = s; s += g_cnt[g][base + i]; }
    int x = s;
#pragma unroll
    for (int o = 1; o < 32; o <<= 1) {
        int y = __shfl_up_sync(0xffffffffu, x, o);
        if (lane >= o) x += y;
    }
    if (lane == 31) wsum[w] = x;
    __syncthreads();
    if (w == 0) {
        int y = wsum[lane];
#pragma unroll
        for (int o = 1; o < 32; o <<= 1) {
            int z = __shfl_up_sync(0xffffffffu, y, o);
            if (lane >= o) y += z;
        }
        wsum[lane] = y;
    }
    __syncthreads();
    int off = x - s + ((w > 0) ? wsum[w - 1] : 0);
#pragma unroll
    for (int i = 0; i < 8; i++) {
        g_rowptr[g][base + i] = off + loc[i];
        g_cursor[g][base + i] = off + loc[i];
    }
    if (t == 1023) g_rowptr[g][NN] = wsum[31];
}
__global__ void k_startsdinv(const int* __restrict__ b1, const int* __restrict__ b2) {
    int g = blockIdx.y;
    int n = blockIdx.x * blockDim.x + threadIdx.x;
    if (n >= NN) return;
    g_dinv[g][n] = rsqrtf(g_deg[g][n] + 1.0f);
    const int* batch = g ? b2 : b1;
    int b = batch[n];
    if (n == 0) {
        for (int bb = 0; bb <= b; bb++) g_starts[g][bb] = 0;
    } else {
        int pb = batch[n - 1];
        if (pb != b) for (int bb = pb + 1; bb <= b; bb++) g_starts[g][bb] = n;
    }
    if (n == NN - 1) for (int bb = b + 1; bb <= NB; bb++) g_starts[g][bb] = NN;
}
__global__ void k_fill(const int* __restrict__ ei1, const float* __restrict__ ew1,
                       const int* __restrict__ ei2, const float* __restrict__ ew2) {
    int g = blockIdx.y;
    const int* ei = g ? ei2 : ei1;
    const float* ew = g ? ew2 : ew1;
    int e = blockIdx.x * blockDim.x + threadIdx.x;
    if (e >= NE) return;
    int s = ei[e], d = ei[NE + e];
    int pos = atomicAdd(&g_cursor[g][d], 1);
    g_csrc[g][pos] = s;
    g_cnrm[g][pos] = g_dinv[g][s] * ew[e] * g_dinv[g][d];
}

// ---------------- bf16 split of Wih right half -> g_Bbuf [3072][1152 u32]: hi|hi|lo ----------------
__global__ void k_bconv(const float* __restrict__ Wih) {
    int i = blockIdx.x * blockDim.x + threadIdx.x;
    if (i >= G4 * (D6 / 2)) return;
    int n = i / (D6 / 2), p = i - n * (D6 / 2);
    const float* wr = Wih + (size_t)n * D12 + D6 + 2 * p;
    float v0 = wr[0], v1 = wr[1];
    __nv_bfloat16 h0 = __float2bfloat16(v0);
    __nv_bfloat16 h1 = __float2bfloat16(v1);
    __nv_bfloat16 l0 = __float2bfloat16(v0 - __bfloat162float(h0));
    __nv_bfloat16 l1 = __float2bfloat16(v1 - __bfloat162float(h1));
    __nv_bfloat162 hp; hp.x = h0; hp.y = h1;
    __nv_bfloat162 lp; lp.x = l0; lp.y = l1;
    uint32_t hu = *(uint32_t*)&hp;
    uint32_t lu = *(uint32_t*)&lp;
    uint32_t* row = g_Bbuf + (size_t)n * (KSPLIT / 2);
    row[p] = hu;                    // seg0: hi(B) (pairs hi(A))
    row[(D6 / 2) + p] = hu;         // seg1: hi(B) (pairs lo(A))
    row[2 * (D6 / 2) + p] = lu;     // seg2: lo(B) (pairs hi(A))
}

// ---------------- gates2 via mma.sync bf16 (hi/lo split) ----------------
// grid (24, 4, 2): block tile 64(M) x 128(N); 8 warps (2m x 4n), warp tile 32x32.
__global__ void __launch_bounds__(256) k_gates2_mma() {
    __shared__ uint32_t A2[64][17];    // 64 rows x 16 u32 (32 bf16) + pad
    __shared__ uint32_t B2[128][17];
    int tid = threadIdx.x, lane = tid & 31, wid = tid >> 5;
    int wm = wid >> 2, wn = wid & 3;
    int colBase = blockIdx.x * 128, rowBase = blockIdx.y * 64, g = blockIdx.z;
    const float* Arow = g_rb[g];
    float c[2][4][4];
#pragma unroll
    for (int mf = 0; mf < 2; mf++)
#pragma unroll
        for (int nf = 0; nf < 4; nf++)
#pragma unroll
            for (int q = 0; q < 4; q++) c[mf][nf][q] = 0.f;

    for (int ch = 0; ch < NCH2; ch++) {
        int seg = ch / 24;
        int koff = (ch - seg * 24) * 32;
        // A: on-the-fly bf16 split of rb (seg==1 -> lo, else hi)
        for (int i = tid; i < 1024; i += 256) {
            int m = i >> 4, p = i & 15;
            float2 v = *(const float2*)(Arow + (size_t)(rowBase + m) * D6 + koff + 2 * p);
            __nv_bfloat16 h0 = __float2bfloat16(v.x);
            __nv_bfloat16 h1 = __float2bfloat16(v.y);
            __nv_bfloat16 o0, o1;
            if (seg == 1) {
                o0 = __float2bfloat16(v.x - __bfloat162float(h0));
                o1 = __float2bfloat16(v.y - __bfloat162float(h1));
            } else { o0 = h0; o1 = h1; }
            __nv_bfloat162 pk; pk.x = o0; pk.y = o1;
            A2[m][p] = *(uint32_t*)&pk;
        }
        // B: prepacked
        {
            int bcol = seg * (D6 / 2) + (koff >> 1);
            for (int i = tid; i < 2048; i += 256) {
                int n = i >> 4, p = i & 15;
                B2[n][p] = g_Bbuf[(size_t)(colBase + n) * (KSPLIT / 2) + bcol + p];
            }
        }
        __syncthreads();
        int q = lane & 3;
        int r0 = wm * 32 + (lane >> 2);
        int nb = wn * 32 + (lane >> 2);
#pragma unroll
        for (int kf = 0; kf < 2; kf++) {
            uint32_t a[2][4];
#pragma unroll
            for (int mf = 0; mf < 2; mf++) {
                int rr = r0 + mf * 16;
                a[mf][0] = A2[rr][q + 8 * kf];
                a[mf][1] = A2[rr + 8][q + 8 * kf];
                a[mf][2] = A2[rr][q + 4 + 8 * kf];
                a[mf][3] = A2[rr + 8][q + 4 + 8 * kf];
            }
#pragma unroll
            for (int nf = 0; nf < 4; nf++) {
                int nn = nb + nf * 8;
                uint32_t b0 = B2[nn][q + 8 * kf];
                uint32_t b1 = B2[nn][q + 4 + 8 * kf];
#pragma unroll
                for (int mf = 0; mf < 2; mf++) {
                    asm volatile(
                        "mma.sync.aligned.m16n8k16.row.col.f32.bf16.bf16.f32 "
                        "{%0,%1,%2,%3}, {%4,%5,%6,%7}, {%8,%9}, {%0,%1,%2,%3};"
                        : "+f"(c[mf][nf][0]), "+f"(c[mf][nf][1]),
                          "+f"(c[mf][nf][2]), "+f"(c[mf][nf][3])
                        : "r"(a[mf][0]), "r"(a[mf][1]), "r"(a[mf][2]), "r"(a[mf][3]),
                          "r"(b0), "r"(b1));
                }
            }
        }
        __syncthreads();
    }
    // epilogue: c0={r,col}, c1={r,col+1}, c2={r+8,col}, c3={r+8,col+1}
    int rloc = (lane >> 2), cloc = (lane & 3) * 2;
#pragma unroll
    for (int mf = 0; mf < 2; mf++) {
#pragma unroll
        for (int nf = 0; nf < 4; nf++) {
            int row = rowBase + wm * 32 + mf * 16 + rloc;
            int col = colBase + wn * 32 + nf * 8 + cloc;
            float* dst = g_gates[g] + (size_t)row * G4 + col;
            dst[0] = c[mf][nf][0] + g_cvec[col];
            dst[1] = c[mf][nf][1] + g_cvec[col + 1];
            float* dst2 = dst + 8 * G4;
            dst2[0] = c[mf][nf][2] + g_cvec[col];
            dst2[1] = c[mf][nf][3] + g_cvec[col + 1];
        }
    }
}

// ---------------- tiled fp32 GEMM (R8 proven): xw ----------------
__global__ void k_gemm_xw(const float* __restrict__ f1, const float* __restrict__ f2,
                          int layer, const float* __restrict__ W) {
    __shared__ float As[16][64];
    __shared__ float Bs[16][68];
    int g = blockIdx.z;
    const float* X;
    int ldx, K;
    if (layer == 0) { X = g ? f2 : f1; ldx = FIN; K = FIN; }
    else            { X = g_h[g] + (layer - 1) * NHF; ldx = H3; K = NHF; }
    int tid = threadIdx.x, tx = tid & 15, ty = tid >> 4;
    int colBase = blockIdx.x * 64, rowBase = blockIdx.y * 64;
    float acc[4][4] = {};
    for (int k0 = 0; k0 < K; k0 += 16) {
#pragma unroll
        for (int l = 0; l < 4; l++) {
            int idx = tid + l * 256;
            int m = idx >> 4, kk = idx & 15;
            As[kk][m] = X[(size_t)(rowBase + m) * ldx + k0 + kk];
            Bs[kk][m] = W[(size_t)(k0 + kk) * NHF + colBase + m];
        }
        __syncthreads();
#pragma unroll
        for (int kk = 0; kk < 16; kk++) {
            float4 a4 = *(const float4*)&As[kk][ty * 4];
            float4 b4 = *(const float4*)&Bs[kk][tx * 4];
            float av[4] = { a4.x, a4.y, a4.z, a4.w };
            float bv[4] = { b4.x, b4.y, b4.z, b4.w };
#pragma unroll
            for (int i = 0; i < 4; i++)
#pragma unroll
                for (int j = 0; j < 4; j++) acc[i][j] += av[i] * bv[j];
        }
        __syncthreads();
    }
#pragma unroll
    for (int i = 0; i < 4; i++)
#pragma unroll
        for (int j = 0; j < 4; j++)
            g_xw[g][(size_t)(rowBase + ty * 4 + i) * NHF + colBase + tx * 4 + j] = acc[i][j];
}

// ---------------- gather (R8 proven; L2 norm fused on last layer) ----------------
template<bool FUSE_L2>
__global__ void k_gather_t(int off, const float* __restrict__ bias) {
    int g = blockIdx.y;
    int n = blockIdx.x * 8 + (threadIdx.x >> 5);
    int lane = threadIdx.x & 31;
    if (n >= NN) return;
    const float4* xw4 = (const float4*)g_xw[g];
    float di = g_dinv[g][n];
    float sn = di * di;
    float4 bb = ((const float4*)bias)[lane];
    float4 sv = xw4[(size_t)n * 32 + lane];
    float ax = bb.x + sn * sv.x, ay = bb.y + sn * sv.y;
    float az = bb.z + sn * sv.z, aw = bb.w + sn * sv.w;
    int e0 = g_rowptr[g][n], e1 = g_rowptr[g][n + 1];
    const int* __restrict__ csrc = g_csrc[g];
    const float* __restrict__ cnrm = g_cnrm[g];
    for (int e = e0; e < e1; e++) {
        int s = csrc[e];
        float nm = cnrm[e];
        float4 v = xw4[(size_t)s * 32 + lane];
        ax += nm * v.x; ay += nm * v.y; az += nm * v.z; aw += nm * v.w;
    }
    ax = (ax >= 0.f) ? ax : 0.2f * ax;
    ay = (ay >= 0.f) ? ay : 0.2f * ay;
    az = (az >= 0.f) ? az : 0.2f * az;
    aw = (aw >= 0.f) ? aw : 0.2f * aw;
    if (!FUSE_L2) {
        float4* o = (float4*)(g_h[g] + (size_t)n * H3 + off);
        o[lane] = make_float4(ax, ay, az, aw);
    } else {
        const float4* hrow = (const float4*)(g_h[g] + (size_t)n * H3);
        float4 v0 = hrow[lane];
        float4 v1 = hrow[lane + 32];
        float ss = v0.x * v0.x + v0.y * v0.y + v0.z * v0.z + v0.w * v0.w
                 + v1.x * v1.x + v1.y * v1.y + v1.z * v1.z + v1.w * v1.w
                 + ax * ax + ay * ay + az * az + aw * aw;
        ss = wredsum(ss);
        float inv = 1.f / fmaxf(sqrtf(ss), 1e-12f);
        float4* xr = (float4*)(g_x[g] + (size_t)n * D6);
        xr[lane]      = make_float4(v0.x * inv, v0.y * inv, v0.z * inv, v0.w * inv);
        xr[lane + 32] = make_float4(v1.x * inv, v1.y * inv, v1.z * inv, v1.w * inv);
        xr[lane + 64] = make_float4(ax * inv, ay * inv, az * inv, aw * inv);
    }
}

// ---------------- interaction (R8 proven) ----------------
__global__ void __launch_bounds__(512) k_interact() {
    int b = blockIdx.x;
    int s1 = g_starts[0][b], e1 = g_starts[0][b + 1];
    int s2 = g_starts[1][b], e2 = g_starts[1][b + 1];
    int n1 = e1 - s1, n2 = e2 - s2, tot = n1 + n2;
    int lane = threadIdx.x & 31, w = threadIdx.x >> 5;
    for (int t = w; t < tot; t += 16) {
        const float *src, *oth;
        float* out;
        int row, obase, ocnt;
        if (t < n1) { row = s1 + t;        src = g_x[0]; oth = g_x[1]; obase = s2; ocnt = n2; out = g_x[0]; }
        else        { row = s2 + (t - n1); src = g_x[1]; oth = g_x[0]; obase = s1; ocnt = n1; out = g_x[1]; }
        const float* sr = src + (size_t)row * D6;
        float sv[12], acc[12];
#pragma unroll
        for (int q = 0; q < 12; q++) { sv[q] = sr[lane + 32 * q]; acc[q] = 0.f; }
        for (int jj = 0; jj < ocnt; jj++) {
            const float* vr = oth + (size_t)(obase + jj) * D6;
            float vv[12], p = 0.f;
#pragma unroll
            for (int q = 0; q < 12; q++) { vv[q] = vr[lane + 32 * q]; p += sv[q] * vv[q]; }
            p = wredsum(p);
#pragma unroll
            for (int q = 0; q < 12; q++) acc[q] += p * vv[q];
        }
        float* orow = out + (size_t)row * D6 + H3;
#pragma unroll
        for (int q = 0; q < 12; q++) orow[lane + 32 * q] = acc[q];
    }
}

// ---------------- cvec + z1pre zero (R8 proven) ----------------
__global__ void k_cvec(const float* __restrict__ Wih, const float* __restrict__ Whh,
                       const float* __restrict__ bih, const float* __restrict__ bhh) {
    __shared__ float shv[D6];
    int tid = threadIdx.x, lane = tid & 31, w = tid >> 5;
    for (int j = tid; j < D6; j += 256) {
        float gi = bih[j] + bhh[j];
        float gg = bih[2 * D6 + j] + bhh[2 * D6 + j];
        float go = bih[3 * D6 + j] + bhh[3 * D6 + j];
        float c = sgm(gi) * tanhf(gg);
        shv[j] = sgm(go) * tanhf(c);
    }
    if (blockIdx.x < 256) g_z1pre[blockIdx.x * 256 + tid] = 0.f;
    __syncthreads();
    int gout = blockIdx.x * 8 + w;
    const float* wi = Wih + (size_t)gout * D12;
    const float* wh = Whh + (size_t)gout * D6;
    float p = 0.f;
#pragma unroll
    for (int t = 0; t < 24; t++) {
        int k = lane + 32 * t;
        p += shv[k] * (wi[k] + wh[k]);
    }
    p = wredsum(p);
    if (lane == 0) g_cvec[gout] = bih[gout] + bhh[gout] + p;
}

// ---------------- attention (R8 proven two-pass) ----------------
__global__ void k_attn1(const float* __restrict__ bih, const float* __restrict__ bhh) {
    __shared__ float hq[D6];
    __shared__ float sc[SMAXSEG];
    __shared__ float red[256];
    int g = blockIdx.y, b = blockIdx.x;
    int tid = threadIdx.x, lane = tid & 31, w = tid >> 5;
    for (int j = tid; j < D6; j += 256) {
        float gi = bih[j] + bhh[j];
        float gg = bih[2 * D6 + j] + bhh[2 * D6 + j];
        float go = bih[3 * D6 + j] + bhh[3 * D6 + j];
        float c = sgm(gi) * tanhf(gg);
        hq[j] = sgm(go) * tanhf(c);
    }
    __syncthreads();
    int s = g_starts[g][b], e = g_starts[g][b + 1], cnt = e - s;
    float* rout = g_rb[g] + (size_t)b * D6;
    if (cnt <= 0) {
        for (int j = tid; j < D6; j += 256) rout[j] = 0.f;
        return;
    }
    const float* x = g_x[g];
    for (int t = w; t < cnt; t += 8) {
        const float* xr = x + (size_t)(s + t) * D6;
        float p = 0.f;
#pragma unroll
        for (int q = 0; q < 24; q++) p += xr[lane + 32 * q] * hq[lane + 32 * q];
        p = wredsum(p);
        if (lane == 0) sc[t] = p;
    }
    __syncthreads();
    float lm = -3.4e38f;
    for (int t = tid; t < cnt; t += 256) lm = fmaxf(lm, sc[t]);
    red[tid] = lm; __syncthreads();
    for (int o = 128; o > 0; o >>= 1) { if (tid < o) red[tid] = fmaxf(red[tid], red[tid + o]); __syncthreads(); }
    float m = red[0]; __syncthreads();
    float ls = 0.f;
    for (int t = tid; t < cnt; t += 256) { float ev = expf(sc[t] - m); sc[t] = ev; ls += ev; }
    red[tid] = ls; __syncthreads();
    for (int o = 128; o > 0; o >>= 1) { if (tid < o) red[tid] += red[tid + o]; __syncthreads(); }
    float S = red[0]; __syncthreads();
    float a0 = 0.f, a1 = 0.f, a2 = 0.f;
    for (int t = 0; t < cnt; t++) {
        float wv = sc[t];
        const float* xr = x + (size_t)(s + t) * D6;
        a0 += wv * xr[tid];
        a1 += wv * xr[tid + 256];
        a2 += wv * xr[tid + 512];
    }
    float inv = 1.f / S;
    rout[tid] = a0 * inv;
    rout[tid + 256] = a1 * inv;
    rout[tid + 512] = a2 * inv;
}

// ---------------- attn step 2 (R8 proven: lstm2 + attention) ----------------
__global__ void k_attn2(const float* __restrict__ bih, const float* __restrict__ bhh) {
    __shared__ float hq[D6];
    __shared__ float sc[SMAXSEG];
    __shared__ float red[256];
    int g = blockIdx.y, b = blockIdx.x;
    int tid = threadIdx.x, lane = tid & 31, w = tid >> 5;
    const float* gt = g_gates[g] + (size_t)b * G4;
    float* zb = g_z + (size_t)b * G4 + (g ? D12 : 0);
    for (int j = tid; j < D6; j += 256) {
        float gi1 = bih[j] + bhh[j];
        float gg1 = bih[2 * D6 + j] + bhh[2 * D6 + j];
        float cv = sgm(gi1) * tanhf(gg1);
        float gi = gt[j], gf = gt[D6 + j], gg = gt[2 * D6 + j], go = gt[3 * D6 + j];
        float c = sgm(gf) * cv + sgm(gi) * tanhf(gg);
        float h = sgm(go) * tanhf(c);
        hq[j] = h;
        zb[j] = h;
    }
    __syncthreads();
    int s = g_starts[g][b], e = g_starts[g][b + 1], cnt = e - s;
    float* rout = zb + D6;
    if (cnt <= 0) {
        for (int j = tid; j < D6; j += 256) rout[j] = 0.f;
        return;
    }
    const float* x = g_x[g];
    for (int t = w; t < cnt; t += 8) {
        const float* xr = x + (size_t)(s + t) * D6;
        float p = 0.f;
#pragma unroll
        for (int q = 0; q < 24; q++) p += xr[lane + 32 * q] * hq[lane + 32 * q];
        p = wredsum(p);
        if (lane == 0) sc[t] = p;
    }
    __syncthreads();
    float lm = -3.4e38f;
    for (int t = tid; t < cnt; t += 256) lm = fmaxf(lm, sc[t]);
    red[tid] = lm; __syncthreads();
    for (int o = 128; o > 0; o >>= 1) { if (tid < o) red[tid] = fmaxf(red[tid], red[tid + o]); __syncthreads(); }
    float m = red[0]; __syncthreads();
    float ls = 0.f;
    for (int t = tid; t < cnt; t += 256) { float ev = expf(sc[t] - m); sc[t] = ev; ls += ev; }
    red[tid] = ls; __syncthreads();
    for (int o = 128; o > 0; o >>= 1) { if (tid < o) red[tid] += red[tid + o]; __syncthreads(); }
    float S = red[0]; __syncthreads();
    float a0 = 0.f, a1 = 0.f, a2 = 0.f;
    for (int t = 0; t < cnt; t++) {
        float wv = sc[t];
        const float* xr = x + (size_t)(s + t) * D6;
        a0 += wv * xr[tid];
        a1 += wv * xr[tid + 256];
        a2 += wv * xr[tid + 512];
    }
    float inv = 1.f / S;
    rout[tid] = a0 * inv;
    rout[tid + 256] = a1 * inv;
    rout[tid + 512] = a2 * inv;
}

// ---------------- MLP head ----------------
__global__ void k_mlp1_gemm(const float* __restrict__ Wp1) {
    __shared__ float As[16][64];
    __shared__ float Bs[16][68];
    int tid = threadIdx.x, tx = tid & 15, ty = tid >> 4;
    int colBase = blockIdx.x * 64, rowBase = blockIdx.y * 64;
    int kBase = blockIdx.z * 128;
    float acc[4][4] = {};
    for (int k0 = 0; k0 < 128; k0 += 16) {
#pragma unroll
        for (int l = 0; l < 4; l++) {
            int idx = tid + l * 256;
            int m = idx >> 4, kk = idx & 15;
            As[kk][m] = g_z[(size_t)(rowBase + m) * G4 + kBase + k0 + kk];
            Bs[kk][m] = Wp1[(size_t)(colBase + m) * G4 + kBase + k0 + kk];
        }
        __syncthreads();
#pragma unroll
        for (int kk = 0; kk < 16; kk++) {
            float4 a4 = *(const float4*)&As[kk][ty * 4];
            float4 b4 = *(const float4*)&Bs[kk][tx * 4];
            float av[4] = { a4.x, a4.y, a4.z, a4.w };
            float bv[4] = { b4.x, b4.y, b4.z, b4.w };
#pragma unroll
            for (int i = 0; i < 4; i++)
#pragma unroll
                for (int j = 0; j < 4; j++) acc[i][j] += av[i] * bv[j];
        }
        __syncthreads();
    }
#pragma unroll
    for (int i = 0; i < 4; i++)
#pragma unroll
        for (int j = 0; j < 4; j++)
            atomicAdd(&g_z1pre[(size_t)(rowBase + ty * 4 + i) * 256 + colBase + tx * 4 + j],
                      acc[i][j]);
}
__global__ void k_mlp2f(const float* __restrict__ bp1,
                        const float* __restrict__ Wp2, const float* __restrict__ bp2,
                        const float* __restrict__ Wp3, const float* __restrict__ bp3,
                        float* __restrict__ out) {
    __shared__ float zs[256];
    __shared__ float z2s[128];
    int b = blockIdx.x, tid = threadIdx.x, lane = tid & 31, w = tid >> 5;
    zs[tid] = fmaxf(g_z1pre[(size_t)b * 256 + tid] + bp1[tid], 0.f);
    __syncthreads();
#pragma unroll
    for (int oo = 0; oo < 16; oo++) {
        int o = w * 16 + oo;
        const float* wr = Wp2 + (size_t)o * 256;
        float p = 0.f;
#pragma unroll
        for (int k = 0; k < 8; k++) p += zs[lane + 32 * k] * wr[lane + 32 * k];
        p = wredsum(p);
        if (lane == 0) z2s[o] = fmaxf(p + bp2[o], 0.f);
    }
    __syncthreads();
    if (w == 0) {
        float p = 0.f;
#pragma unroll
        for (int k = 0; k < 4; k++) p += z2s[lane + 32 * k] * Wp3[lane + 32 * k];
        p = wredsum(p);
        if (lane == 0) out[b] = 1.f / (1.f + expf(-p - bp3[0]));
    }
}

// ---------------- launch sequence ----------------
extern "C" void kernel_launch(void* const* d_in, const int* in_sizes, int n_in,
                              void* d_out, int out_size) {
    const float* f1 = (const float*)d_in[0];
    const float* f2 = (const float*)d_in[1];
    const float* ea1 = (const float*)d_in[2];
    const float* ea2 = (const float*)d_in[3];
    const float* W[3]  = { (const float*)d_in[4], (const float*)d_in[6], (const float*)d_in[8] };
    const float* bW[3] = { (const float*)d_in[5], (const float*)d_in[7], (const float*)d_in[9] };
    const float* Wih = (const float*)d_in[10];
    const float* bih = (const float*)d_in[11];
    const float* Whh = (const float*)d_in[12];
    const float* bhh = (const float*)d_in[13];
    const float* Wp1 = (const float*)d_in[14];
    const float* bp1 = (const float*)d_in[15];
    const float* Wp2 = (const float*)d_in[16];
    const float* bp2 = (const float*)d_in[17];
    const float* Wp3 = (const float*)d_in[18];
    const float* bp3 = (const float*)d_in[19];
    const int* ei1 = (const int*)d_in[20];
    const int* ei2 = (const int*)d_in[21];
    const int* b1 = (const int*)d_in[22];
    const int* b2 = (const int*)d_in[23];
    float* out = (float*)d_out;

    static cudaStream_t s1 = (cudaStream_t)0;
    static cudaEvent_t evA, evB;
    static bool inited = false;
    if (!inited) {
        cudaStreamCreateWithFlags(&s1, cudaStreamNonBlocking);
        cudaEventCreateWithFlags(&evA, cudaEventDisableTiming);
        cudaEventCreateWithFlags(&evB, cudaEventDisableTiming);
        inited = true;
    }
    cudaStream_t s0 = (cudaStream_t)0;
    const int T = 256;

    // side stream: B bf16 split + CSR build, overlapped with cvec + layer-0 GEMM
    cudaEventRecord(evA, s0);
    cudaStreamWaitEvent(s1, evA, 0);
    k_bconv<<<(G4 * (D6 / 2)) / T, T, 0, s1>>>(Wih);
    k_prep<<<2 * NN / T, T, 0, s1>>>();
    k_count<<<dim3(NE / T, 2), T, 0, s1>>>(ei1, ea1, ei2, ea2);
    k_scan<<<2, 1024, 0, s1>>>();
    k_startsdinv<<<dim3(NN / T, 2), T, 0, s1>>>(b1, b2);
    k_fill<<<dim3(NE / T, 2), T, 0, s1>>>(ei1, ea1, ei2, ea2);
    cudaEventRecord(evB, s1);

    k_cvec<<<G4 / 8, T, 0, s0>>>(Wih, Whh, bih, bhh);
    k_gemm_xw<<<dim3(2, NN / 64, 2), T, 0, s0>>>(f1, f2, 0, W[0]);

    cudaStreamWaitEvent(s0, evB, 0);
    k_gather_t<false><<<dim3(NN / 8, 2), T, 0, s0>>>(0, bW[0]);
    k_gemm_xw<<<dim3(2, NN / 64, 2), T, 0, s0>>>(f1, f2, 1, W[1]);
    k_gather_t<false><<<dim3(NN / 8, 2), T, 0, s0>>>(NHF, bW[1]);
    k_gemm_xw<<<dim3(2, NN / 64, 2), T, 0, s0>>>(f1, f2, 2, W[2]);
    k_gather_t<true><<<dim3(NN / 8, 2), T, 0, s0>>>(2 * NHF, bW[2]);
    k_interact<<<NB, 512, 0, s0>>>();

    k_attn1<<<dim3(NB, 2), T, 0, s0>>>(bih, bhh);
    k_gates2_mma<<<dim3(G4 / 128, NB / 64, 2), T, 0, s0>>>();
    k_attn2<<<dim3(NB, 2), T, 0, s0>>>(bih, bhh);

    k_mlp1_gemm<<<dim3(4, 4, 24), T, 0, s0>>>(Wp1);
    k_mlp2f<<<NB, T, 0, s0>>>(bp1, Wp2, bp2, Wp3, bp3, out);
}

// round 15
// speedup vs baseline: 1.2221x; 1.2221x over previous
#include <cuda_runtime.h>
#include <cuda_bf16.h>
#include <cstdint>

#define NN   8192
#define NE   131072
#define NB   256
#define NHF  128
#define FIN  64
#define H3   384
#define D6   768
#define D12  1536
#define G4   3072
#define SMAXSEG 512
#define KSPLIT 2304
#define KU    (KSPLIT / 2)   // 1152 u32 per packed row
#define NCH   36             // K-chunks of 64 bf16 (32 u32)

// ---------------- scratch ----------------
__device__ __align__(16) float g_h[2][NN * H3];
__device__ __align__(16) float g_x[2][NN * D6];
__device__ __align__(16) float g_xw[2][NN * NHF];
__device__ float g_deg[2][NN];
__device__ int   g_cnt[2][NN];
__device__ int   g_cursor[2][NN];
__device__ int   g_rowptr[2][NN + 1];
__device__ int   g_csrc[2][NE];
__device__ float g_cnrm[2][NE];
__device__ float g_dinv[2][NN];
__device__ int   g_starts[2][NB + 1];
__device__ float g_cvec[G4];
__device__ __align__(16) float g_rb[2][NB * D6];
__device__ __align__(16) float g_gates[2][NB * G4];
__device__ __align__(16) float g_z[NB * G4];
__device__ __align__(16) float g_z1pre[NB * 256];
__device__ __align__(16) uint32_t g_Bbuf[G4 * KU];        // B': hi|hi|lo per row
__device__ __align__(16) uint32_t g_Abuf[2][NB * KU];     // A': hi|lo|hi per row

__device__ __forceinline__ float wredsum(float v) {
#pragma unroll
    for (int o = 16; o; o >>= 1) v += __shfl_xor_sync(0xffffffffu, v, o);
    return v;
}
__device__ __forceinline__ float sgm(float x) { return 1.f / (1.f + expf(-x)); }
__device__ __forceinline__ uint32_t bf16pack(float a, float b) {
    __nv_bfloat162 p; p.x = __float2bfloat16(a); p.y = __float2bfloat16(b);
    return *(uint32_t*)&p;
}

// ---------------- CSR build (R8 proven) ----------------
__global__ void k_prep() {
    int i = blockIdx.x * blockDim.x + threadIdx.x;
    if (i < 2 * NN) {
        int g = i >> 13, n = i & (NN - 1);
        g_cnt[g][n] = 0;
        g_deg[g][n] = 0.f;
    }
}
__global__ void k_count(const int* __restrict__ ei1, const float* __restrict__ ew1,
                        const int* __restrict__ ei2, const float* __restrict__ ew2) {
    int g = blockIdx.y;
    const int* ei = g ? ei2 : ei1;
    const float* ew = g ? ew2 : ew1;
    int e = blockIdx.x * blockDim.x + threadIdx.x;
    if (e < NE) {
        int d = ei[NE + e];
        atomicAdd(&g_cnt[g][d], 1);
        atomicAdd(&g_deg[g][d], ew[e]);
    }
}
__global__ void k_scan() {
    __shared__ int wsum[32];
    int g = blockIdx.x;
    int t = threadIdx.x, lane = t & 31, w = t >> 5;
    int base = t * 8;
    int loc[8], s = 0;
#pragma unroll
    for (int i = 0; i < 8; i++) { loc[i] = s; s += g_cnt[g][base + i]; }
    int x = s;
#pragma unroll
    for (int o = 1; o < 32; o <<= 1) {
        int y = __shfl_up_sync(0xffffffffu, x, o);
        if (lane >= o) x += y;
    }
    if (lane == 31) wsum[w] = x;
    __syncthreads();
    if (w == 0) {
        int y = wsum[lane];
#pragma unroll
        for (int o = 1; o < 32; o <<= 1) {
            int z = __shfl_up_sync(0xffffffffu, y, o);
            if (lane >= o) y += z;
        }
        wsum[lane] = y;
    }
    __syncthreads();
    int off = x - s + ((w > 0) ? wsum[w - 1] : 0);
#pragma unroll
    for (int i = 0; i < 8; i++) {
        g_rowptr[g][base + i] = off + loc[i];
        g_cursor[g][base + i] = off + loc[i];
    }
    if (t == 1023) g_rowptr[g][NN] = wsum[31];
}
__global__ void k_startsdinv(const int* __restrict__ b1, const int* __restrict__ b2) {
    int g = blockIdx.y;
    int n = blockIdx.x * blockDim.x + threadIdx.x;
    if (n >= NN) return;
    g_dinv[g][n] = rsqrtf(g_deg[g][n] + 1.0f);
    const int* batch = g ? b2 : b1;
    int b = batch[n];
    if (n == 0) {
        for (int bb = 0; bb <= b; bb++) g_starts[g][bb] = 0;
    } else {
        int pb = batch[n - 1];
        if (pb != b) for (int bb = pb + 1; bb <= b; bb++) g_starts[g][bb] = n;
    }
    if (n == NN - 1) for (int bb = b + 1; bb <= NB; bb++) g_starts[g][bb] = NN;
}
__global__ void k_fill(const int* __restrict__ ei1, const float* __restrict__ ew1,
                       const int* __restrict__ ei2, const float* __restrict__ ew2) {
    int g = blockIdx.y;
    const int* ei = g ? ei2 : ei1;
    const float* ew = g ? ew2 : ew1;
    int e = blockIdx.x * blockDim.x + threadIdx.x;
    if (e >= NE) return;
    int s = ei[e], d = ei[NE + e];
    int pos = atomicAdd(&g_cursor[g][d], 1);
    g_csrc[g][pos] = s;
    g_cnrm[g][pos] = g_dinv[g][s] * ew[e] * g_dinv[g][d];
}

// ---------------- B split: Wih right half -> g_Bbuf hi|hi|lo ----------------
__global__ void k_bconv(const float* __restrict__ Wih) {
    int i = blockIdx.x * blockDim.x + threadIdx.x;
    if (i >= G4 * (D6 / 2)) return;
    int n = i / (D6 / 2), p = i - n * (D6 / 2);
    const float* wr = Wih + (size_t)n * D12 + D6 + 2 * p;
    float v0 = wr[0], v1 = wr[1];
    __nv_bfloat16 h0 = __float2bfloat16(v0);
    __nv_bfloat16 h1 = __float2bfloat16(v1);
    uint32_t hu = bf16pack(v0, v1);
    uint32_t lu = bf16pack(v0 - __bfloat162float(h0), v1 - __bfloat162float(h1));
    uint32_t* row = g_Bbuf + (size_t)n * KU;
    row[p] = hu;
    row[(D6 / 2) + p] = hu;
    row[2 * (D6 / 2) + p] = lu;
}

// ---------------- gates2 via mma.sync + ldmatrix (packed A', B') ----------------
// grid (24, 2, 2): block 128x128; 8 warps (2m x 4n); warp 64x32; K-chunks of 32 u32.
__global__ void __launch_bounds__(256) k_gates2_mma() {
    __shared__ __align__(16) uint32_t As[128][36];
    __shared__ __align__(16) uint32_t Bs[128][36];
    int tid = threadIdx.x, lane = tid & 31, wid = tid >> 5;
    int wm = wid >> 2, wn = wid & 3;
    int colBase = blockIdx.x * 128, rowBase = blockIdx.y * 128, g = blockIdx.z;
    const uint32_t* Abuf = g_Abuf[g];
    float c[4][4][4];
#pragma unroll
    for (int mf = 0; mf < 4; mf++)
#pragma unroll
        for (int nf = 0; nf < 4; nf++)
#pragma unroll
            for (int q = 0; q < 4; q++) c[mf][nf][q] = 0.f;

    // ldmatrix lane addresses (byte offsets computed per use)
    uint32_t aBase = (uint32_t)__cvta_generic_to_shared(&As[0][0]);
    uint32_t bBase = (uint32_t)__cvta_generic_to_shared(&Bs[0][0]);

    for (int ch = 0; ch < NCH; ch++) {
        __syncthreads();
#pragma unroll
        for (int l = 0; l < 4; l++) {
            int i = tid + l * 256;              // 1024 uint4 per operand
            int m = i >> 3, p = i & 7;
            *(uint4*)&As[m][p * 4] = *(const uint4*)&Abuf[(size_t)(rowBase + m) * KU + ch * 32 + p * 4];
            *(uint4*)&Bs[m][p * 4] = *(const uint4*)&g_Bbuf[(size_t)(colBase + m) * KU + ch * 32 + p * 4];
        }
        __syncthreads();
#pragma unroll
        for (int kf = 0; kf < 4; kf++) {
            uint32_t a[4][4];
#pragma unroll
            for (int mf = 0; mf < 4; mf++) {
                int row = wm * 64 + mf * 16 + (lane & 15);
                uint32_t addr = aBase + (row * 36 + kf * 8 + (lane >> 4) * 4) * 4;
                asm volatile("ldmatrix.sync.aligned.m8n8.x4.shared.b16 {%0,%1,%2,%3}, [%4];"
                             : "=r"(a[mf][0]), "=r"(a[mf][1]), "=r"(a[mf][2]), "=r"(a[mf][3])
                             : "r"(addr));
            }
#pragma unroll
            for (int nf = 0; nf < 4; nf++) {
                int nrow = wn * 32 + nf * 8 + (lane & 7);
                uint32_t addr = bBase + (nrow * 36 + kf * 8 + ((lane >> 3) & 1) * 4) * 4;
                uint32_t b0, b1;
                asm volatile("ldmatrix.sync.aligned.m8n8.x2.shared.b16 {%0,%1}, [%2];"
                             : "=r"(b0), "=r"(b1) : "r"(addr));
#pragma unroll
                for (int mf = 0; mf < 4; mf++) {
                    asm volatile(
                        "mma.sync.aligned.m16n8k16.row.col.f32.bf16.bf16.f32 "
                        "{%0,%1,%2,%3}, {%4,%5,%6,%7}, {%8,%9}, {%0,%1,%2,%3};"
                        : "+f"(c[mf][nf][0]), "+f"(c[mf][nf][1]),
                          "+f"(c[mf][nf][2]), "+f"(c[mf][nf][3])
                        : "r"(a[mf][0]), "r"(a[mf][1]), "r"(a[mf][2]), "r"(a[mf][3]),
                          "r"(b0), "r"(b1));
                }
            }
        }
    }
    int rloc = lane >> 2, cloc = (lane & 3) * 2;
#pragma unroll
    for (int mf = 0; mf < 4; mf++) {
#pragma unroll
        for (int nf = 0; nf < 4; nf++) {
            int row = rowBase + wm * 64 + mf * 16 + rloc;
            int col = colBase + wn * 32 + nf * 8 + cloc;
            float* dst = g_gates[g] + (size_t)row * G4 + col;
            dst[0] = c[mf][nf][0] + g_cvec[col];
            dst[1] = c[mf][nf][1] + g_cvec[col + 1];
            float* dst2 = dst + 8 * G4;
            dst2[0] = c[mf][nf][2] + g_cvec[col];
            dst2[1] = c[mf][nf][3] + g_cvec[col + 1];
        }
    }
}

// ---------------- tiled fp32 GEMM (R8 proven): xw ----------------
__global__ void k_gemm_xw(const float* __restrict__ f1, const float* __restrict__ f2,
                          int layer, const float* __restrict__ W) {
    __shared__ float As[16][64];
    __shared__ float Bs[16][68];
    int g = blockIdx.z;
    const float* X;
    int ldx, K;
    if (layer == 0) { X = g ? f2 : f1; ldx = FIN; K = FIN; }
    else            { X = g_h[g] + (layer - 1) * NHF; ldx = H3; K = NHF; }
    int tid = threadIdx.x, tx = tid & 15, ty = tid >> 4;
    int colBase = blockIdx.x * 64, rowBase = blockIdx.y * 64;
    float acc[4][4] = {};
    for (int k0 = 0; k0 < K; k0 += 16) {
#pragma unroll
        for (int l = 0; l < 4; l++) {
            int idx = tid + l * 256;
            int m = idx >> 4, kk = idx & 15;
            As[kk][m] = X[(size_t)(rowBase + m) * ldx + k0 + kk];
            Bs[kk][m] = W[(size_t)(k0 + kk) * NHF + colBase + m];
        }
        __syncthreads();
#pragma unroll
        for (int kk = 0; kk < 16; kk++) {
            float4 a4 = *(const float4*)&As[kk][ty * 4];
            float4 b4 = *(const float4*)&Bs[kk][tx * 4];
            float av[4] = { a4.x, a4.y, a4.z, a4.w };
            float bv[4] = { b4.x, b4.y, b4.z, b4.w };
#pragma unroll
            for (int i = 0; i < 4; i++)
#pragma unroll
                for (int j = 0; j < 4; j++) acc[i][j] += av[i] * bv[j];
        }
        __syncthreads();
    }
#pragma unroll
    for (int i = 0; i < 4; i++)
#pragma unroll
        for (int j = 0; j < 4; j++)
            g_xw[g][(size_t)(rowBase + ty * 4 + i) * NHF + colBase + tx * 4 + j] = acc[i][j];
}

// ---------------- gather (R8 proven; L2 norm fused on last layer) ----------------
template<bool FUSE_L2>
__global__ void k_gather_t(int off, const float* __restrict__ bias) {
    int g = blockIdx.y;
    int n = blockIdx.x * 8 + (threadIdx.x >> 5);
    int lane = threadIdx.x & 31;
    if (n >= NN) return;
    const float4* xw4 = (const float4*)g_xw[g];
    float di = g_dinv[g][n];
    float sn = di * di;
    float4 bb = ((const float4*)bias)[lane];
    float4 sv = xw4[(size_t)n * 32 + lane];
    float ax = bb.x + sn * sv.x, ay = bb.y + sn * sv.y;
    float az = bb.z + sn * sv.z, aw = bb.w + sn * sv.w;
    int e0 = g_rowptr[g][n], e1 = g_rowptr[g][n + 1];
    const int* __restrict__ csrc = g_csrc[g];
    const float* __restrict__ cnrm = g_cnrm[g];
    for (int e = e0; e < e1; e++) {
        int s = csrc[e];
        float nm = cnrm[e];
        float4 v = xw4[(size_t)s * 32 + lane];
        ax += nm * v.x; ay += nm * v.y; az += nm * v.z; aw += nm * v.w;
    }
    ax = (ax >= 0.f) ? ax : 0.2f * ax;
    ay = (ay >= 0.f) ? ay : 0.2f * ay;
    az = (az >= 0.f) ? az : 0.2f * az;
    aw = (aw >= 0.f) ? aw : 0.2f * aw;
    if (!FUSE_L2) {
        float4* o = (float4*)(g_h[g] + (size_t)n * H3 + off);
        o[lane] = make_float4(ax, ay, az, aw);
    } else {
        const float4* hrow = (const float4*)(g_h[g] + (size_t)n * H3);
        float4 v0 = hrow[lane];
        float4 v1 = hrow[lane + 32];
        float ss = v0.x * v0.x + v0.y * v0.y + v0.z * v0.z + v0.w * v0.w
                 + v1.x * v1.x + v1.y * v1.y + v1.z * v1.z + v1.w * v1.w
                 + ax * ax + ay * ay + az * az + aw * aw;
        ss = wredsum(ss);
        float inv = 1.f / fmaxf(sqrtf(ss), 1e-12f);
        float4* xr = (float4*)(g_x[g] + (size_t)n * D6);
        xr[lane]      = make_float4(v0.x * inv, v0.y * inv, v0.z * inv, v0.w * inv);
        xr[lane + 32] = make_float4(v1.x * inv, v1.y * inv, v1.z * inv, v1.w * inv);
        xr[lane + 64] = make_float4(ax * inv, ay * inv, az * inv, aw * inv);
    }
}

// ---------------- interaction (R8 proven) ----------------
__global__ void __launch_bounds__(512) k_interact() {
    int b = blockIdx.x;
    int s1 = g_starts[0][b], e1 = g_starts[0][b + 1];
    int s2 = g_starts[1][b], e2 = g_starts[1][b + 1];
    int n1 = e1 - s1, n2 = e2 - s2, tot = n1 + n2;
    int lane = threadIdx.x & 31, w = threadIdx.x >> 5;
    for (int t = w; t < tot; t += 16) {
        const float *src, *oth;
        float* out;
        int row, obase, ocnt;
        if (t < n1) { row = s1 + t;        src = g_x[0]; oth = g_x[1]; obase = s2; ocnt = n2; out = g_x[0]; }
        else        { row = s2 + (t - n1); src = g_x[1]; oth = g_x[0]; obase = s1; ocnt = n1; out = g_x[1]; }
        const float* sr = src + (size_t)row * D6;
        float sv[12], acc[12];
#pragma unroll
        for (int q = 0; q < 12; q++) { sv[q] = sr[lane + 32 * q]; acc[q] = 0.f; }
        for (int jj = 0; jj < ocnt; jj++) {
            const float* vr = oth + (size_t)(obase + jj) * D6;
            float vv[12], p = 0.f;
#pragma unroll
            for (int q = 0; q < 12; q++) { vv[q] = vr[lane + 32 * q]; p += sv[q] * vv[q]; }
            p = wredsum(p);
#pragma unroll
            for (int q = 0; q < 12; q++) acc[q] += p * vv[q];
        }
        float* orow = out + (size_t)row * D6 + H3;
#pragma unroll
        for (int q = 0; q < 12; q++) orow[lane + 32 * q] = acc[q];
    }
}

// ---------------- cvec + z1pre zero (R8 proven) ----------------
__global__ void k_cvec(const float* __restrict__ Wih, const float* __restrict__ Whh,
                       const float* __restrict__ bih, const float* __restrict__ bhh) {
    __shared__ float shv[D6];
    int tid = threadIdx.x, lane = tid & 31, w = tid >> 5;
    for (int j = tid; j < D6; j += 256) {
        float gi = bih[j] + bhh[j];
        float gg = bih[2 * D6 + j] + bhh[2 * D6 + j];
        float go = bih[3 * D6 + j] + bhh[3 * D6 + j];
        float c = sgm(gi) * tanhf(gg);
        shv[j] = sgm(go) * tanhf(c);
    }
    if (blockIdx.x < 256) g_z1pre[blockIdx.x * 256 + tid] = 0.f;
    __syncthreads();
    int gout = blockIdx.x * 8 + w;
    const float* wi = Wih + (size_t)gout * D12;
    const float* wh = Whh + (size_t)gout * D6;
    float p = 0.f;
#pragma unroll
    for (int t = 0; t < 24; t++) {
        int k = lane + 32 * t;
        p += shv[k] * (wi[k] + wh[k]);
    }
    p = wredsum(p);
    if (lane == 0) g_cvec[gout] = bih[gout] + bhh[gout] + p;
}

// ---------------- attn step 1 (R8 proven) + A' bf16 split epilogue ----------------
__global__ void k_attn1(const float* __restrict__ bih, const float* __restrict__ bhh) {
    __shared__ float hq[D6];
    __shared__ float sc[SMAXSEG];
    __shared__ float red[256];
    int g = blockIdx.y, b = blockIdx.x;
    int tid = threadIdx.x, lane = tid & 31, w = tid >> 5;
    uint32_t* arow = g_Abuf[g] + (size_t)b * KU;
    for (int j = tid; j < D6; j += 256) {
        float gi = bih[j] + bhh[j];
        float gg = bih[2 * D6 + j] + bhh[2 * D6 + j];
        float go = bih[3 * D6 + j] + bhh[3 * D6 + j];
        float c = sgm(gi) * tanhf(gg);
        hq[j] = sgm(go) * tanhf(c);
    }
    __syncthreads();
    int s = g_starts[g][b], e = g_starts[g][b + 1], cnt = e - s;
    float* rout = g_rb[g] + (size_t)b * D6;
    if (cnt <= 0) {
        for (int j = tid; j < D6; j += 256) rout[j] = 0.f;
        for (int j = tid; j < KU; j += 256) arow[j] = 0u;
        return;
    }
    const float* x = g_x[g];
    for (int t = w; t < cnt; t += 8) {
        const float* xr = x + (size_t)(s + t) * D6;
        float p = 0.f;
#pragma unroll
        for (int q = 0; q < 24; q++) p += xr[lane + 32 * q] * hq[lane + 32 * q];
        p = wredsum(p);
        if (lane == 0) sc[t] = p;
    }
    __syncthreads();
    float lm = -3.4e38f;
    for (int t = tid; t < cnt; t += 256) lm = fmaxf(lm, sc[t]);
    red[tid] = lm; __syncthreads();
    for (int o = 128; o > 0; o >>= 1) { if (tid < o) red[tid] = fmaxf(red[tid], red[tid + o]); __syncthreads(); }
    float m = red[0]; __syncthreads();
    float ls = 0.f;
    for (int t = tid; t < cnt; t += 256) { float ev = expf(sc[t] - m); sc[t] = ev; ls += ev; }
    red[tid] = ls; __syncthreads();
    for (int o = 128; o > 0; o >>= 1) { if (tid < o) red[tid] += red[tid + o]; __syncthreads(); }
    float S = red[0]; __syncthreads();
    float a0 = 0.f, a1 = 0.f, a2 = 0.f;
    for (int t = 0; t < cnt; t++) {
        float wv = sc[t];
        const float* xr = x + (size_t)(s + t) * D6;
        a0 += wv * xr[tid];
        a1 += wv * xr[tid + 256];
        a2 += wv * xr[tid + 512];
    }
    float inv = 1.f / S;
    rout[tid] = a0 * inv;
    rout[tid + 256] = a1 * inv;
    rout[tid + 512] = a2 * inv;
    __syncthreads();   // rout visible block-wide
    // A' split: hi | lo | hi  (pairs of consecutive floats)
    for (int p = tid; p < D6 / 2; p += 256) {
        float v0 = rout[2 * p], v1 = rout[2 * p + 1];
        __nv_bfloat16 h0 = __float2bfloat16(v0);
        __nv_bfloat16 h1 = __float2bfloat16(v1);
        uint32_t hu = bf16pack(v0, v1);
        uint32_t lu = bf16pack(v0 - __bfloat162float(h0), v1 - __bfloat162float(h1));
        arow[p] = hu;
        arow[(D6 / 2) + p] = lu;
        arow[2 * (D6 / 2) + p] = hu;
    }
}

// ---------------- attn step 2 (R8 proven: lstm2 + attention) ----------------
__global__ void k_attn2(const float* __restrict__ bih, const float* __restrict__ bhh) {
    __shared__ float hq[D6];
    __shared__ float sc[SMAXSEG];
    __shared__ float red[256];
    int g = blockIdx.y, b = blockIdx.x;
    int tid = threadIdx.x, lane = tid & 31, w = tid >> 5;
    const float* gt = g_gates[g] + (size_t)b * G4;
    float* zb = g_z + (size_t)b * G4 + (g ? D12 : 0);
    for (int j = tid; j < D6; j += 256) {
        float gi1 = bih[j] + bhh[j];
        float gg1 = bih[2 * D6 + j] + bhh[2 * D6 + j];
        float cv = sgm(gi1) * tanhf(gg1);
        float gi = gt[j], gf = gt[D6 + j], gg = gt[2 * D6 + j], go = gt[3 * D6 + j];
        float c = sgm(gf) * cv + sgm(gi) * tanhf(gg);
        float h = sgm(go) * tanhf(c);
        hq[j] = h;
        zb[j] = h;
    }
    __syncthreads();
    int s = g_starts[g][b], e = g_starts[g][b + 1], cnt = e - s;
    float* rout = zb + D6;
    if (cnt <= 0) {
        for (int j = tid; j < D6; j += 256) rout[j] = 0.f;
        return;
    }
    const float* x = g_x[g];
    for (int t = w; t < cnt; t += 8) {
        const float* xr = x + (size_t)(s + t) * D6;
        float p = 0.f;
#pragma unroll
        for (int q = 0; q < 24; q++) p += xr[lane + 32 * q] * hq[lane + 32 * q];
        p = wredsum(p);
        if (lane == 0) sc[t] = p;
    }
    __syncthreads();
    float lm = -3.4e38f;
    for (int t = tid; t < cnt; t += 256) lm = fmaxf(lm, sc[t]);
    red[tid] = lm; __syncthreads();
    for (int o = 128; o > 0; o >>= 1) { if (tid < o) red[tid] = fmaxf(red[tid], red[tid + o]); __syncthreads(); }
    float m = red[0]; __syncthreads();
    float ls = 0.f;
    for (int t = tid; t < cnt; t += 256) { float ev = expf(sc[t] - m); sc[t] = ev; ls += ev; }
    red[tid] = ls; __syncthreads();
    for (int o = 128; o > 0; o >>= 1) { if (tid < o) red[tid] += red[tid + o]; __syncthreads(); }
    float S = red[0]; __syncthreads();
    float a0 = 0.f, a1 = 0.f, a2 = 0.f;
    for (int t = 0; t < cnt; t++) {
        float wv = sc[t];
        const float* xr = x + (size_t)(s + t) * D6;
        a0 += wv * xr[tid];
        a1 += wv * xr[tid + 256];
        a2 += wv * xr[tid + 512];
    }
    float inv = 1.f / S;
    rout[tid] = a0 * inv;
    rout[tid + 256] = a1 * inv;
    rout[tid + 512] = a2 * inv;
}

// ---------------- MLP head ----------------
__global__ void k_mlp1_gemm(const float* __restrict__ Wp1) {
    __shared__ float As[16][64];
    __shared__ float Bs[16][68];
    int tid = threadIdx.x, tx = tid & 15, ty = tid >> 4;
    int colBase = blockIdx.x * 64, rowBase = blockIdx.y * 64;
    int kBase = blockIdx.z * 128;
    float acc[4][4] = {};
    for (int k0 = 0; k0 < 128; k0 += 16) {
#pragma unroll
        for (int l = 0; l < 4; l++) {
            int idx = tid + l * 256;
            int m = idx >> 4, kk = idx & 15;
            As[kk][m] = g_z[(size_t)(rowBase + m) * G4 + kBase + k0 + kk];
            Bs[kk][m] = Wp1[(size_t)(colBase + m) * G4 + kBase + k0 + kk];
        }
        __syncthreads();
#pragma unroll
        for (int kk = 0; kk < 16; kk++) {
            float4 a4 = *(const float4*)&As[kk][ty * 4];
            float4 b4 = *(const float4*)&Bs[kk][tx * 4];
            float av[4] = { a4.x, a4.y, a4.z, a4.w };
            float bv[4] = { b4.x, b4.y, b4.z, b4.w };
#pragma unroll
            for (int i = 0; i < 4; i++)
#pragma unroll
                for (int j = 0; j < 4; j++) acc[i][j] += av[i] * bv[j];
        }
        __syncthreads();
    }
#pragma unroll
    for (int i = 0; i < 4; i++)
#pragma unroll
        for (int j = 0; j < 4; j++)
            atomicAdd(&g_z1pre[(size_t)(rowBase + ty * 4 + i) * 256 + colBase + tx * 4 + j],
                      acc[i][j]);
}
__global__ void k_mlp2f(const float* __restrict__ bp1,
                        const float* __restrict__ Wp2, const float* __restrict__ bp2,
                        const float* __restrict__ Wp3, const float* __restrict__ bp3,
                        float* __restrict__ out) {
    __shared__ float zs[256];
    __shared__ float z2s[128];
    int b = blockIdx.x, tid = threadIdx.x, lane = tid & 31, w = tid >> 5;
    zs[tid] = fmaxf(g_z1pre[(size_t)b * 256 + tid] + bp1[tid], 0.f);
    __syncthreads();
#pragma unroll
    for (int oo = 0; oo < 16; oo++) {
        int o = w * 16 + oo;
        const float* wr = Wp2 + (size_t)o * 256;
        float p = 0.f;
#pragma unroll
        for (int k = 0; k < 8; k++) p += zs[lane + 32 * k] * wr[lane + 32 * k];
        p = wredsum(p);
        if (lane == 0) z2s[o] = fmaxf(p + bp2[o], 0.f);
    }
    __syncthreads();
    if (w == 0) {
        float p = 0.f;
#pragma unroll
        for (int k = 0; k < 4; k++) p += z2s[lane + 32 * k] * Wp3[lane + 32 * k];
        p = wredsum(p);
        if (lane == 0) out[b] = 1.f / (1.f + expf(-p - bp3[0]));
    }
}

// ---------------- launch sequence ----------------
extern "C" void kernel_launch(void* const* d_in, const int* in_sizes, int n_in,
                              void* d_out, int out_size) {
    const float* f1 = (const float*)d_in[0];
    const float* f2 = (const float*)d_in[1];
    const float* ea1 = (const float*)d_in[2];
    const float* ea2 = (const float*)d_in[3];
    const float* W[3]  = { (const float*)d_in[4], (const float*)d_in[6], (const float*)d_in[8] };
    const float* bW[3] = { (const float*)d_in[5], (const float*)d_in[7], (const float*)d_in[9] };
    const float* Wih = (const float*)d_in[10];
    const float* bih = (const float*)d_in[11];
    const float* Whh = (const float*)d_in[12];
    const float* bhh = (const float*)d_in[13];
    const float* Wp1 = (const float*)d_in[14];
    const float* bp1 = (const float*)d_in[15];
    const float* Wp2 = (const float*)d_in[16];
    const float* bp2 = (const float*)d_in[17];
    const float* Wp3 = (const float*)d_in[18];
    const float* bp3 = (const float*)d_in[19];
    const int* ei1 = (const int*)d_in[20];
    const int* ei2 = (const int*)d_in[21];
    const int* b1 = (const int*)d_in[22];
    const int* b2 = (const int*)d_in[23];
    float* out = (float*)d_out;

    static cudaStream_t s1 = (cudaStream_t)0;
    static cudaEvent_t evA, evB;
    static bool inited = false;
    if (!inited) {
        cudaStreamCreateWithFlags(&s1, cudaStreamNonBlocking);
        cudaEventCreateWithFlags(&evA, cudaEventDisableTiming);
        cudaEventCreateWithFlags(&evB, cudaEventDisableTiming);
        inited = true;
    }
    cudaStream_t s0 = (cudaStream_t)0;
    const int T = 256;

    // side stream: B split + CSR build, overlapped with cvec + layer-0 GEMM
    cudaEventRecord(evA, s0);
    cudaStreamWaitEvent(s1, evA, 0);
    k_bconv<<<(G4 * (D6 / 2)) / T, T, 0, s1>>>(Wih);
    k_prep<<<2 * NN / T, T, 0, s1>>>();
    k_count<<<dim3(NE / T, 2), T, 0, s1>>>(ei1, ea1, ei2, ea2);
    k_scan<<<2, 1024, 0, s1>>>();
    k_startsdinv<<<dim3(NN / T, 2), T, 0, s1>>>(b1, b2);
    k_fill<<<dim3(NE / T, 2), T, 0, s1>>>(ei1, ea1, ei2, ea2);
    cudaEventRecord(evB, s1);

    k_cvec<<<G4 / 8, T, 0, s0>>>(Wih, Whh, bih, bhh);
    k_gemm_xw<<<dim3(2, NN / 64, 2), T, 0, s0>>>(f1, f2, 0, W[0]);

    cudaStreamWaitEvent(s0, evB, 0);
    k_gather_t<false><<<dim3(NN / 8, 2), T, 0, s0>>>(0, bW[0]);
    k_gemm_xw<<<dim3(2, NN / 64, 2), T, 0, s0>>>(f1, f2, 1, W[1]);
    k_gather_t<false><<<dim3(NN / 8, 2), T, 0, s0>>>(NHF, bW[1]);
    k_gemm_xw<<<dim3(2, NN / 64, 2), T, 0, s0>>>(f1, f2, 2, W[2]);
    k_gather_t<true><<<dim3(NN / 8, 2), T, 0, s0>>>(2 * NHF, bW[2]);
    k_interact<<<NB, 512, 0, s0>>>();

    k_attn1<<<dim3(NB, 2), T, 0, s0>>>(bih, bhh);
    k_gates2_mma<<<dim3(G4 / 128, 2, 2), T, 0, s0>>>();
    k_attn2<<<dim3(NB, 2), T, 0, s0>>>(bih, bhh);

    k_mlp1_gemm<<<dim3(4, 4, 24), T, 0, s0>>>(Wp1);
    k_mlp2f<<<NB, T, 0, s0>>>(bp1, Wp2, bp2, Wp3, bp3, out);
}

// round 16
// speedup vs baseline: 1.2594x; 1.0305x over previous
#include <cuda_runtime.h>
#include <cuda_bf16.h>
#include <cstdint>

#define NN   8192
#define NE   131072
#define NB   256
#define NHF  128
#define FIN  64
#define H3   384
#define D6   768
#define D12  1536
#define G4   3072
#define SMAXSEG 512
#define KSPLIT 2304
#define KU    (KSPLIT / 2)   // 1152 u32 per packed gates2 row
#define NCH   36

// ---------------- scratch ----------------
__device__ __align__(16) float g_h[2][NN * H3];
__device__ __align__(16) float g_x[2][NN * D6];
__device__ __align__(16) float g_xw[2][NN * NHF];
__device__ float g_deg[2][NN];
__device__ int   g_cnt[2][NN];
__device__ int   g_cursor[2][NN];
__device__ int   g_rowptr[2][NN + 1];
__device__ int   g_csrc[2][NE];
__device__ float g_cnrm[2][NE];
__device__ float g_dinv[2][NN];
__device__ int   g_starts[2][NB + 1];
__device__ float g_cvec[G4];
__device__ __align__(16) float g_rb[2][NB * D6];
__device__ __align__(16) float g_gates[2][NB * G4];
__device__ __align__(16) float g_z[NB * G4];
__device__ __align__(16) float g_z1pre[NB * 256];
__device__ __align__(16) uint32_t g_Bbuf[G4 * KU];        // gates2 B': hi|hi|lo
__device__ __align__(16) uint32_t g_Abuf[2][NB * KU];     // gates2 A': hi|lo|hi
__device__ __align__(16) uint32_t g_Wbuf[3][NHF * 192];   // xw W': hi|hi|lo (stride 192 u32)
__device__ __align__(16) uint32_t g_P1buf[256 * 4608];    // mlp1 Wp1': hi|hi|lo

__device__ __forceinline__ float wredsum(float v) {
#pragma unroll
    for (int o = 16; o; o >>= 1) v += __shfl_xor_sync(0xffffffffu, v, o);
    return v;
}
__device__ __forceinline__ float sgm(float x) { return 1.f / (1.f + expf(-x)); }
__device__ __forceinline__ uint32_t bf16pack(float a, float b) {
    __nv_bfloat162 p; p.x = __float2bfloat16(a); p.y = __float2bfloat16(b);
    return *(uint32_t*)&p;
}
__device__ __forceinline__ uint32_t bf16lo(float a, float b) {
    __nv_bfloat16 h0 = __float2bfloat16(a);
    __nv_bfloat16 h1 = __float2bfloat16(b);
    return bf16pack(a - __bfloat162float(h0), b - __bfloat162float(h1));
}

// ---------------- CSR build (proven) ----------------
__global__ void k_prep() {
    int i = blockIdx.x * blockDim.x + threadIdx.x;
    if (i < 2 * NN) {
        int g = i >> 13, n = i & (NN - 1);
        g_cnt[g][n] = 0;
        g_deg[g][n] = 0.f;
    }
}
__global__ void k_count(const int* __restrict__ ei1, const float* __restrict__ ew1,
                        const int* __restrict__ ei2, const float* __restrict__ ew2) {
    int g = blockIdx.y;
    const int* ei = g ? ei2 : ei1;
    const float* ew = g ? ew2 : ew1;
    int e = blockIdx.x * blockDim.x + threadIdx.x;
    if (e < NE) {
        int d = ei[NE + e];
        atomicAdd(&g_cnt[g][d], 1);
        atomicAdd(&g_deg[g][d], ew[e]);
    }
}
__global__ void k_scan() {
    __shared__ int wsum[32];
    int g = blockIdx.x;
    int t = threadIdx.x, lane = t & 31, w = t >> 5;
    int base = t * 8;
    int loc[8], s = 0;
#pragma unroll
    for (int i = 0; i < 8; i++) { loc[i] = s; s += g_cnt[g][base + i]; }
    int x = s;
#pragma unroll
    for (int o = 1; o < 32; o <<= 1) {
        int y = __shfl_up_sync(0xffffffffu, x, o);
        if (lane >= o) x += y;
    }
    if (lane == 31) wsum[w] = x;
    __syncthreads();
    if (w == 0) {
        int y = wsum[lane];
#pragma unroll
        for (int o = 1; o < 32; o <<= 1) {
            int z = __shfl_up_sync(0xffffffffu, y, o);
            if (lane >= o) y += z;
        }
        wsum[lane] = y;
    }
    __syncthreads();
    int off = x - s + ((w > 0) ? wsum[w - 1] : 0);
#pragma unroll
    for (int i = 0; i < 8; i++) {
        g_rowptr[g][base + i] = off + loc[i];
        g_cursor[g][base + i] = off + loc[i];
    }
    if (t == 1023) g_rowptr[g][NN] = wsum[31];
}
__global__ void k_startsdinv(const int* __restrict__ b1, const int* __restrict__ b2) {
    int g = blockIdx.y;
    int n = blockIdx.x * blockDim.x + threadIdx.x;
    if (n >= NN) return;
    g_dinv[g][n] = rsqrtf(g_deg[g][n] + 1.0f);
    const int* batch = g ? b2 : b1;
    int b = batch[n];
    if (n == 0) {
        for (int bb = 0; bb <= b; bb++) g_starts[g][bb] = 0;
    } else {
        int pb = batch[n - 1];
        if (pb != b) for (int bb = pb + 1; bb <= b; bb++) g_starts[g][bb] = n;
    }
    if (n == NN - 1) for (int bb = b + 1; bb <= NB; bb++) g_starts[g][bb] = NN;
}
__global__ void k_fill(const int* __restrict__ ei1, const float* __restrict__ ew1,
                       const int* __restrict__ ei2, const float* __restrict__ ew2) {
    int g = blockIdx.y;
    const int* ei = g ? ei2 : ei1;
    const float* ew = g ? ew2 : ew1;
    int e = blockIdx.x * blockDim.x + threadIdx.x;
    if (e >= NE) return;
    int s = ei[e], d = ei[NE + e];
    int pos = atomicAdd(&g_cursor[g][d], 1);
    g_csrc[g][pos] = s;
    g_cnrm[g][pos] = g_dinv[g][s] * ew[e] * g_dinv[g][d];
}

// ---------------- operand pre-splits (side stream; weights are static) ----------------
__global__ void k_bconv(const float* __restrict__ Wih) {
    int i = blockIdx.x * blockDim.x + threadIdx.x;
    if (i >= G4 * (D6 / 2)) return;
    int n = i / (D6 / 2), p = i - n * (D6 / 2);
    const float* wr = Wih + (size_t)n * D12 + D6 + 2 * p;
    float v0 = wr[0], v1 = wr[1];
    uint32_t hu = bf16pack(v0, v1);
    uint32_t lu = bf16lo(v0, v1);
    uint32_t* row = g_Bbuf + (size_t)n * KU;
    row[p] = hu;
    row[(D6 / 2) + p] = hu;
    row[2 * (D6 / 2) + p] = lu;
}
// xw W split: W[K,128] -> g_Wbuf[l][n][hi(K/2)|hi|lo], row stride 192 u32
__global__ void k_wconv(int l, int K, const float* __restrict__ W) {
    int i = blockIdx.x * blockDim.x + threadIdx.x;
    int half = K / 2;
    if (i >= NHF * half) return;
    int n = i / half, p = i - n * half;
    float v0 = W[(size_t)(2 * p) * NHF + n];
    float v1 = W[(size_t)(2 * p + 1) * NHF + n];
    uint32_t hu = bf16pack(v0, v1);
    uint32_t lu = bf16lo(v0, v1);
    uint32_t* row = g_Wbuf[l] + (size_t)n * 192;
    row[p] = hu;
    row[half + p] = hu;
    row[2 * half + p] = lu;
}
// mlp1 Wp1 split: Wp1[256,3072] -> g_P1buf[o][hi(1536)|hi|lo]
__global__ void k_p1conv(const float* __restrict__ Wp1) {
    int i = blockIdx.x * blockDim.x + threadIdx.x;
    if (i >= 256 * 1536) return;
    int o = i / 1536, p = i - o * 1536;
    const float* wr = Wp1 + (size_t)o * G4 + 2 * p;
    float v0 = wr[0], v1 = wr[1];
    uint32_t hu = bf16pack(v0, v1);
    uint32_t lu = bf16lo(v0, v1);
    uint32_t* row = g_P1buf + (size_t)o * 4608;
    row[p] = hu;
    row[1536 + p] = hu;
    row[3072 + p] = lu;
}

// ---------------- shared mma tile core (validated in R15) ----------------
// As/Bs: [128][36] u32; 8 warps 2m x 4n; warp 64x32; one K-chunk = 32 u32 (64 bf16).
struct MmaAcc { float c[4][4][4]; };
__device__ __forceinline__ void mma_chunk(uint32_t aBase, uint32_t bBase,
                                          int lane, int wm, int wn, MmaAcc& A) {
#pragma unroll
    for (int kf = 0; kf < 4; kf++) {
        uint32_t a[4][4];
#pragma unroll
        for (int mf = 0; mf < 4; mf++) {
            int row = wm * 64 + mf * 16 + (lane & 15);
            uint32_t addr = aBase + (row * 36 + kf * 8 + (lane >> 4) * 4) * 4;
            asm volatile("ldmatrix.sync.aligned.m8n8.x4.shared.b16 {%0,%1,%2,%3}, [%4];"
                         : "=r"(a[mf][0]), "=r"(a[mf][1]), "=r"(a[mf][2]), "=r"(a[mf][3])
                         : "r"(addr));
        }
#pragma unroll
        for (int nf = 0; nf < 4; nf++) {
            int nrow = wn * 32 + nf * 8 + (lane & 7);
            uint32_t addr = bBase + (nrow * 36 + kf * 8 + ((lane >> 3) & 1) * 4) * 4;
            uint32_t b0, b1;
            asm volatile("ldmatrix.sync.aligned.m8n8.x2.shared.b16 {%0,%1}, [%2];"
                         : "=r"(b0), "=r"(b1) : "r"(addr));
#pragma unroll
            for (int mf = 0; mf < 4; mf++) {
                asm volatile(
                    "mma.sync.aligned.m16n8k16.row.col.f32.bf16.bf16.f32 "
                    "{%0,%1,%2,%3}, {%4,%5,%6,%7}, {%8,%9}, {%0,%1,%2,%3};"
                    : "+f"(A.c[mf][nf][0]), "+f"(A.c[mf][nf][1]),
                      "+f"(A.c[mf][nf][2]), "+f"(A.c[mf][nf][3])
                    : "r"(a[mf][0]), "r"(a[mf][1]), "r"(a[mf][2]), "r"(a[mf][3]),
                      "r"(b0), "r"(b1));
            }
        }
    }
}

// ---------------- gates2 (R15 proven, refactored onto mma_chunk) ----------------
__global__ void __launch_bounds__(256) k_gates2_mma() {
    __shared__ __align__(16) uint32_t As[128][36];
    __shared__ __align__(16) uint32_t Bs[128][36];
    int tid = threadIdx.x, lane = tid & 31, wid = tid >> 5;
    int wm = wid >> 2, wn = wid & 3;
    int colBase = blockIdx.x * 128, rowBase = blockIdx.y * 128, g = blockIdx.z;
    const uint32_t* Abuf = g_Abuf[g];
    MmaAcc acc;
#pragma unroll
    for (int mf = 0; mf < 4; mf++)
#pragma unroll
        for (int nf = 0; nf < 4; nf++)
#pragma unroll
            for (int q = 0; q < 4; q++) acc.c[mf][nf][q] = 0.f;
    uint32_t aBase = (uint32_t)__cvta_generic_to_shared(&As[0][0]);
    uint32_t bBase = (uint32_t)__cvta_generic_to_shared(&Bs[0][0]);
    for (int ch = 0; ch < NCH; ch++) {
        __syncthreads();
#pragma unroll
        for (int l = 0; l < 4; l++) {
            int i = tid + l * 256;
            int m = i >> 3, p = i & 7;
            *(uint4*)&As[m][p * 4] = *(const uint4*)&Abuf[(size_t)(rowBase + m) * KU + ch * 32 + p * 4];
            *(uint4*)&Bs[m][p * 4] = *(const uint4*)&g_Bbuf[(size_t)(colBase + m) * KU + ch * 32 + p * 4];
        }
        __syncthreads();
        mma_chunk(aBase, bBase, lane, wm, wn, acc);
    }
    int rloc = lane >> 2, cloc = (lane & 3) * 2;
#pragma unroll
    for (int mf = 0; mf < 4; mf++) {
#pragma unroll
        for (int nf = 0; nf < 4; nf++) {
            int row = rowBase + wm * 64 + mf * 16 + rloc;
            int col = colBase + wn * 32 + nf * 8 + cloc;
            float* dst = g_gates[g] + (size_t)row * G4 + col;
            dst[0] = acc.c[mf][nf][0] + g_cvec[col];
            dst[1] = acc.c[mf][nf][1] + g_cvec[col + 1];
            float* dst2 = dst + 8 * G4;
            dst2[0] = acc.c[mf][nf][2] + g_cvec[col];
            dst2[1] = acc.c[mf][nf][3] + g_cvec[col + 1];
        }
    }
}

// ---------------- xw via mma: g_xw[g] = X[8192,K] @ W[K,128], hi/lo split ----------------
// grid (64, 2): 128-row tiles; single 128-col tile. K' = 3K; chunks of 64 bf16.
__global__ void __launch_bounds__(256) k_xw_mma(const float* __restrict__ f1,
                                                const float* __restrict__ f2,
                                                int layer) {
    __shared__ __align__(16) uint32_t As[128][36];
    __shared__ __align__(16) uint32_t Bs[128][36];
    int tid = threadIdx.x, lane = tid & 31, wid = tid >> 5;
    int wm = wid >> 2, wn = wid & 3;
    int rowBase = blockIdx.x * 128, g = blockIdx.y;
    const float* X;
    int ldx, K;
    if (layer == 0) { X = g ? f2 : f1; ldx = FIN; K = FIN; }
    else            { X = g_h[g] + (layer - 1) * NHF; ldx = H3; K = NHF; }
    int segch = K / 64;                 // chunks per segment (1 or 2)
    int nch = 3 * segch;
    const uint32_t* Wb = g_Wbuf[layer];
    MmaAcc acc;
#pragma unroll
    for (int mf = 0; mf < 4; mf++)
#pragma unroll
        for (int nf = 0; nf < 4; nf++)
#pragma unroll
            for (int q = 0; q < 4; q++) acc.c[mf][nf][q] = 0.f;
    uint32_t aBase = (uint32_t)__cvta_generic_to_shared(&As[0][0]);
    uint32_t bBase = (uint32_t)__cvta_generic_to_shared(&Bs[0][0]);
    for (int ch = 0; ch < nch; ch++) {
        int seg = ch / segch;
        int koff = (ch - seg * segch) * 64;
        __syncthreads();
#pragma unroll
        for (int l = 0; l < 4; l++) {
            int i = tid + l * 256;
            int m = i >> 3, p = i & 7;
            // A: 8 floats -> 4 packed u32 (seg 1 -> lo, else hi)
            const float* src = X + (size_t)(rowBase + m) * ldx + koff + p * 8;
            float4 f0 = *(const float4*)src;
            float4 f1v = *(const float4*)(src + 4);
            uint4 o;
            if (seg == 1) {
                o.x = bf16lo(f0.x, f0.y); o.y = bf16lo(f0.z, f0.w);
                o.z = bf16lo(f1v.x, f1v.y); o.w = bf16lo(f1v.z, f1v.w);
            } else {
                o.x = bf16pack(f0.x, f0.y); o.y = bf16pack(f0.z, f0.w);
                o.z = bf16pack(f1v.x, f1v.y); o.w = bf16pack(f1v.z, f1v.w);
            }
            *(uint4*)&As[m][p * 4] = o;
            // B: prepacked
            *(uint4*)&Bs[m][p * 4] = *(const uint4*)&Wb[(size_t)m * 192 + ch * 32 + p * 4];
        }
        __syncthreads();
        mma_chunk(aBase, bBase, lane, wm, wn, acc);
    }
    int rloc = lane >> 2, cloc = (lane & 3) * 2;
#pragma unroll
    for (int mf = 0; mf < 4; mf++) {
#pragma unroll
        for (int nf = 0; nf < 4; nf++) {
            int row = rowBase + wm * 64 + mf * 16 + rloc;
            int col = wn * 32 + nf * 8 + cloc;
            float* dst = g_xw[g] + (size_t)row * NHF + col;
            dst[0] = acc.c[mf][nf][0];
            dst[1] = acc.c[mf][nf][1];
            float* dst2 = dst + 8 * NHF;
            dst2[0] = acc.c[mf][nf][2];
            dst2[1] = acc.c[mf][nf][3];
        }
    }
}

// ---------------- mlp1 via mma: z1pre += z @ Wp1^T, hi/lo split, split-K ----------------
// grid (2, 2, 12): 128x128 tiles, 12 chunks each (144 total over K'=9216).
__global__ void __launch_bounds__(256) k_mlp1_mma() {
    __shared__ __align__(16) uint32_t As[128][36];
    __shared__ __align__(16) uint32_t Bs[128][36];
    int tid = threadIdx.x, lane = tid & 31, wid = tid >> 5;
    int wm = wid >> 2, wn = wid & 3;
    int colBase = blockIdx.x * 128, rowBase = blockIdx.y * 128;
    MmaAcc acc;
#pragma unroll
    for (int mf = 0; mf < 4; mf++)
#pragma unroll
        for (int nf = 0; nf < 4; nf++)
#pragma unroll
            for (int q = 0; q < 4; q++) acc.c[mf][nf][q] = 0.f;
    uint32_t aBase = (uint32_t)__cvta_generic_to_shared(&As[0][0]);
    uint32_t bBase = (uint32_t)__cvta_generic_to_shared(&Bs[0][0]);
    for (int ci = 0; ci < 12; ci++) {
        int ch = blockIdx.z * 12 + ci;
        int seg = ch / 48;
        int koff = (ch - seg * 48) * 64;
        __syncthreads();
#pragma unroll
        for (int l = 0; l < 4; l++) {
            int i = tid + l * 256;
            int m = i >> 3, p = i & 7;
            const float* src = g_z + (size_t)(rowBase + m) * G4 + koff + p * 8;
            float4 f0 = *(const float4*)src;
            float4 f1v = *(const float4*)(src + 4);
            uint4 o;
            if (seg == 1) {
                o.x = bf16lo(f0.x, f0.y); o.y = bf16lo(f0.z, f0.w);
                o.z = bf16lo(f1v.x, f1v.y); o.w = bf16lo(f1v.z, f1v.w);
            } else {
                o.x = bf16pack(f0.x, f0.y); o.y = bf16pack(f0.z, f0.w);
                o.z = bf16pack(f1v.x, f1v.y); o.w = bf16pack(f1v.z, f1v.w);
            }
            *(uint4*)&As[m][p * 4] = o;
            *(uint4*)&Bs[m][p * 4] = *(const uint4*)&g_P1buf[(size_t)(colBase + m) * 4608 + ch * 32 + p * 4];
        }
        __syncthreads();
        mma_chunk(aBase, bBase, lane, wm, wn, acc);
    }
    int rloc = lane >> 2, cloc = (lane & 3) * 2;
#pragma unroll
    for (int mf = 0; mf < 4; mf++) {
#pragma unroll
        for (int nf = 0; nf < 4; nf++) {
            int row = rowBase + wm * 64 + mf * 16 + rloc;
            int col = colBase + wn * 32 + nf * 8 + cloc;
            float* dst = g_z1pre + (size_t)row * 256 + col;
            atomicAdd(&dst[0], acc.c[mf][nf][0]);
            atomicAdd(&dst[1], acc.c[mf][nf][1]);
            float* dst2 = dst + 8 * 256;
            atomicAdd(&dst2[0], acc.c[mf][nf][2]);
            atomicAdd(&dst2[1], acc.c[mf][nf][3]);
        }
    }
}

// ---------------- gather (R8 proven; L2 norm fused on last layer) ----------------
template<bool FUSE_L2>
__global__ void k_gather_t(int off, const float* __restrict__ bias) {
    int g = blockIdx.y;
    int n = blockIdx.x * 8 + (threadIdx.x >> 5);
    int lane = threadIdx.x & 31;
    if (n >= NN) return;
    const float4* xw4 = (const float4*)g_xw[g];
    float di = g_dinv[g][n];
    float sn = di * di;
    float4 bb = ((const float4*)bias)[lane];
    float4 sv = xw4[(size_t)n * 32 + lane];
    float ax = bb.x + sn * sv.x, ay = bb.y + sn * sv.y;
    float az = bb.z + sn * sv.z, aw = bb.w + sn * sv.w;
    int e0 = g_rowptr[g][n], e1 = g_rowptr[g][n + 1];
    const int* __restrict__ csrc = g_csrc[g];
    const float* __restrict__ cnrm = g_cnrm[g];
    for (int e = e0; e < e1; e++) {
        int s = csrc[e];
        float nm = cnrm[e];
        float4 v = xw4[(size_t)s * 32 + lane];
        ax += nm * v.x; ay += nm * v.y; az += nm * v.z; aw += nm * v.w;
    }
    ax = (ax >= 0.f) ? ax : 0.2f * ax;
    ay = (ay >= 0.f) ? ay : 0.2f * ay;
    az = (az >= 0.f) ? az : 0.2f * az;
    aw = (aw >= 0.f) ? aw : 0.2f * aw;
    if (!FUSE_L2) {
        float4* o = (float4*)(g_h[g] + (size_t)n * H3 + off);
        o[lane] = make_float4(ax, ay, az, aw);
    } else {
        const float4* hrow = (const float4*)(g_h[g] + (size_t)n * H3);
        float4 v0 = hrow[lane];
        float4 v1 = hrow[lane + 32];
        float ss = v0.x * v0.x + v0.y * v0.y + v0.z * v0.z + v0.w * v0.w
                 + v1.x * v1.x + v1.y * v1.y + v1.z * v1.z + v1.w * v1.w
                 + ax * ax + ay * ay + az * az + aw * aw;
        ss = wredsum(ss);
        float inv = 1.f / fmaxf(sqrtf(ss), 1e-12f);
        float4* xr = (float4*)(g_x[g] + (size_t)n * D6);
        xr[lane]      = make_float4(v0.x * inv, v0.y * inv, v0.z * inv, v0.w * inv);
        xr[lane + 32] = make_float4(v1.x * inv, v1.y * inv, v1.z * inv, v1.w * inv);
        xr[lane + 64] = make_float4(ax * inv, ay * inv, az * inv, aw * inv);
    }
}

// ---------------- interaction (R8 proven) ----------------
__global__ void __launch_bounds__(512) k_interact() {
    int b = blockIdx.x;
    int s1 = g_starts[0][b], e1 = g_starts[0][b + 1];
    int s2 = g_starts[1][b], e2 = g_starts[1][b + 1];
    int n1 = e1 - s1, n2 = e2 - s2, tot = n1 + n2;
    int lane = threadIdx.x & 31, w = threadIdx.x >> 5;
    for (int t = w; t < tot; t += 16) {
        const float *src, *oth;
        float* out;
        int row, obase, ocnt;
        if (t < n1) { row = s1 + t;        src = g_x[0]; oth = g_x[1]; obase = s2; ocnt = n2; out = g_x[0]; }
        else        { row = s2 + (t - n1); src = g_x[1]; oth = g_x[0]; obase = s1; ocnt = n1; out = g_x[1]; }
        const float* sr = src + (size_t)row * D6;
        float sv[12], acc[12];
#pragma unroll
        for (int q = 0; q < 12; q++) { sv[q] = sr[lane + 32 * q]; acc[q] = 0.f; }
        for (int jj = 0; jj < ocnt; jj++) {
            const float* vr = oth + (size_t)(obase + jj) * D6;
            float vv[12], p = 0.f;
#pragma unroll
            for (int q = 0; q < 12; q++) { vv[q] = vr[lane + 32 * q]; p += sv[q] * vv[q]; }
            p = wredsum(p);
#pragma unroll
            for (int q = 0; q < 12; q++) acc[q] += p * vv[q];
        }
        float* orow = out + (size_t)row * D6 + H3;
#pragma unroll
        for (int q = 0; q < 12; q++) orow[lane + 32 * q] = acc[q];
    }
}

// ---------------- cvec + z1pre zero (R8 proven) ----------------
__global__ void k_cvec(const float* __restrict__ Wih, const float* __restrict__ Whh,
                       const float* __restrict__ bih, const float* __restrict__ bhh) {
    __shared__ float shv[D6];
    int tid = threadIdx.x, lane = tid & 31, w = tid >> 5;
    for (int j = tid; j < D6; j += 256) {
        float gi = bih[j] + bhh[j];
        float gg = bih[2 * D6 + j] + bhh[2 * D6 + j];
        float go = bih[3 * D6 + j] + bhh[3 * D6 + j];
        float c = sgm(gi) * tanhf(gg);
        shv[j] = sgm(go) * tanhf(c);
    }
    if (blockIdx.x < 256) g_z1pre[blockIdx.x * 256 + tid] = 0.f;
    __syncthreads();
    int gout = blockIdx.x * 8 + w;
    const float* wi = Wih + (size_t)gout * D12;
    const float* wh = Whh + (size_t)gout * D6;
    float p = 0.f;
#pragma unroll
    for (int t = 0; t < 24; t++) {
        int k = lane + 32 * t;
        p += shv[k] * (wi[k] + wh[k]);
    }
    p = wredsum(p);
    if (lane == 0) g_cvec[gout] = bih[gout] + bhh[gout] + p;
}

// ---------------- attn step 1 (R15 proven, with A' epilogue) ----------------
__global__ void k_attn1(const float* __restrict__ bih, const float* __restrict__ bhh) {
    __shared__ float hq[D6];
    __shared__ float sc[SMAXSEG];
    __shared__ float red[256];
    int g = blockIdx.y, b = blockIdx.x;
    int tid = threadIdx.x, lane = tid & 31, w = tid >> 5;
    uint32_t* arow = g_Abuf[g] + (size_t)b * KU;
    for (int j = tid; j < D6; j += 256) {
        float gi = bih[j] + bhh[j];
        float gg = bih[2 * D6 + j] + bhh[2 * D6 + j];
        float go = bih[3 * D6 + j] + bhh[3 * D6 + j];
        float c = sgm(gi) * tanhf(gg);
        hq[j] = sgm(go) * tanhf(c);
    }
    __syncthreads();
    int s = g_starts[g][b], e = g_starts[g][b + 1], cnt = e - s;
    float* rout = g_rb[g] + (size_t)b * D6;
    if (cnt <= 0) {
        for (int j = tid; j < D6; j += 256) rout[j] = 0.f;
        for (int j = tid; j < KU; j += 256) arow[j] = 0u;
        return;
    }
    const float* x = g_x[g];
    for (int t = w; t < cnt; t += 8) {
        const float* xr = x + (size_t)(s + t) * D6;
        float p = 0.f;
#pragma unroll
        for (int q = 0; q < 24; q++) p += xr[lane + 32 * q] * hq[lane + 32 * q];
        p = wredsum(p);
        if (lane == 0) sc[t] = p;
    }
    __syncthreads();
    float lm = -3.4e38f;
    for (int t = tid; t < cnt; t += 256) lm = fmaxf(lm, sc[t]);
    red[tid] = lm; __syncthreads();
    for (int o = 128; o > 0; o >>= 1) { if (tid < o) red[tid] = fmaxf(red[tid], red[tid + o]); __syncthreads(); }
    float m = red[0]; __syncthreads();
    float ls = 0.f;
    for (int t = tid; t < cnt; t += 256) { float ev = expf(sc[t] - m); sc[t] = ev; ls += ev; }
    red[tid] = ls; __syncthreads();
    for (int o = 128; o > 0; o >>= 1) { if (tid < o) red[tid] += red[tid + o]; __syncthreads(); }
    float S = red[0]; __syncthreads();
    float a0 = 0.f, a1 = 0.f, a2 = 0.f;
    for (int t = 0; t < cnt; t++) {
        float wv = sc[t];
        const float* xr = x + (size_t)(s + t) * D6;
        a0 += wv * xr[tid];
        a1 += wv * xr[tid + 256];
        a2 += wv * xr[tid + 512];
    }
    float inv = 1.f / S;
    rout[tid] = a0 * inv;
    rout[tid + 256] = a1 * inv;
    rout[tid + 512] = a2 * inv;
    __syncthreads();
    for (int p = tid; p < D6 / 2; p += 256) {
        float v0 = rout[2 * p], v1 = rout[2 * p + 1];
        uint32_t hu = bf16pack(v0, v1);
        uint32_t lu = bf16lo(v0, v1);
        arow[p] = hu;
        arow[(D6 / 2) + p] = lu;
        arow[2 * (D6 / 2) + p] = hu;
    }
}

// ---------------- attn step 2 (R8 proven) ----------------
__global__ void k_attn2(const float* __restrict__ bih, const float* __restrict__ bhh) {
    __shared__ float hq[D6];
    __shared__ float sc[SMAXSEG];
    __shared__ float red[256];
    int g = blockIdx.y, b = blockIdx.x;
    int tid = threadIdx.x, lane = tid & 31, w = tid >> 5;
    const float* gt = g_gates[g] + (size_t)b * G4;
    float* zb = g_z + (size_t)b * G4 + (g ? D12 : 0);
    for (int j = tid; j < D6; j += 256) {
        float gi1 = bih[j] + bhh[j];
        float gg1 = bih[2 * D6 + j] + bhh[2 * D6 + j];
        float cv = sgm(gi1) * tanhf(gg1);
        float gi = gt[j], gf = gt[D6 + j], gg = gt[2 * D6 + j], go = gt[3 * D6 + j];
        float c = sgm(gf) * cv + sgm(gi) * tanhf(gg);
        float h = sgm(go) * tanhf(c);
        hq[j] = h;
        zb[j] = h;
    }
    __syncthreads();
    int s = g_starts[g][b], e = g_starts[g][b + 1], cnt = e - s;
    float* rout = zb + D6;
    if (cnt <= 0) {
        for (int j = tid; j < D6; j += 256) rout[j] = 0.f;
        return;
    }
    const float* x = g_x[g];
    for (int t = w; t < cnt; t += 8) {
        const float* xr = x + (size_t)(s + t) * D6;
        float p = 0.f;
#pragma unroll
        for (int q = 0; q < 24; q++) p += xr[lane + 32 * q] * hq[lane + 32 * q];
        p = wredsum(p);
        if (lane == 0) sc[t] = p;
    }
    __syncthreads();
    float lm = -3.4e38f;
    for (int t = tid; t < cnt; t += 256) lm = fmaxf(lm, sc[t]);
    red[tid] = lm; __syncthreads();
    for (int o = 128; o > 0; o >>= 1) { if (tid < o) red[tid] = fmaxf(red[tid], red[tid + o]); __syncthreads(); }
    float m = red[0]; __syncthreads();
    float ls = 0.f;
    for (int t = tid; t < cnt; t += 256) { float ev = expf(sc[t] - m); sc[t] = ev; ls += ev; }
    red[tid] = ls; __syncthreads();
    for (int o = 128; o > 0; o >>= 1) { if (tid < o) red[tid] += red[tid + o]; __syncthreads(); }
    float S = red[0]; __syncthreads();
    float a0 = 0.f, a1 = 0.f, a2 = 0.f;
    for (int t = 0; t < cnt; t++) {
        float wv = sc[t];
        const float* xr = x + (size_t)(s + t) * D6;
        a0 += wv * xr[tid];
        a1 += wv * xr[tid + 256];
        a2 += wv * xr[tid + 512];
    }
    float inv = 1.f / S;
    rout[tid] = a0 * inv;
    rout[tid + 256] = a1 * inv;
    rout[tid + 512] = a2 * inv;
}

// ---------------- MLP tail (R9/R15 proven) ----------------
__global__ void k_mlp2f(const float* __restrict__ bp1,
                        const float* __restrict__ Wp2, const float* __restrict__ bp2,
                        const float* __restrict__ Wp3, const float* __restrict__ bp3,
                        float* __restrict__ out) {
    __shared__ float zs[256];
    __shared__ float z2s[128];
    int b = blockIdx.x, tid = threadIdx.x, lane = tid & 31, w = tid >> 5;
    zs[tid] = fmaxf(g_z1pre[(size_t)b * 256 + tid] + bp1[tid], 0.f);
    __syncthreads();
#pragma unroll
    for (int oo = 0; oo < 16; oo++) {
        int o = w * 16 + oo;
        const float* wr = Wp2 + (size_t)o * 256;
        float p = 0.f;
#pragma unroll
        for (int k = 0; k < 8; k++) p += zs[lane + 32 * k] * wr[lane + 32 * k];
        p = wredsum(p);
        if (lane == 0) z2s[o] = fmaxf(p + bp2[o], 0.f);
    }
    __syncthreads();
    if (w == 0) {
        float p = 0.f;
#pragma unroll
        for (int k = 0; k < 4; k++) p += z2s[lane + 32 * k] * Wp3[lane + 32 * k];
        p = wredsum(p);
        if (lane == 0) out[b] = 1.f / (1.f + expf(-p - bp3[0]));
    }
}

// ---------------- launch sequence ----------------
extern "C" void kernel_launch(void* const* d_in, const int* in_sizes, int n_in,
                              void* d_out, int out_size) {
    const float* f1 = (const float*)d_in[0];
    const float* f2 = (const float*)d_in[1];
    const float* ea1 = (const float*)d_in[2];
    const float* ea2 = (const float*)d_in[3];
    const float* W[3]  = { (const float*)d_in[4], (const float*)d_in[6], (const float*)d_in[8] };
    const float* bW[3] = { (const float*)d_in[5], (const float*)d_in[7], (const float*)d_in[9] };
    const float* Wih = (const float*)d_in[10];
    const float* bih = (const float*)d_in[11];
    const float* Whh = (const float*)d_in[12];
    const float* bhh = (const float*)d_in[13];
    const float* Wp1 = (const float*)d_in[14];
    const float* bp1 = (const float*)d_in[15];
    const float* Wp2 = (const float*)d_in[16];
    const float* bp2 = (const float*)d_in[17];
    const float* Wp3 = (const float*)d_in[18];
    const float* bp3 = (const float*)d_in[19];
    const int* ei1 = (const int*)d_in[20];
    const int* ei2 = (const int*)d_in[21];
    const int* b1 = (const int*)d_in[22];
    const int* b2 = (const int*)d_in[23];
    float* out = (float*)d_out;

    static cudaStream_t s1 = (cudaStream_t)0;
    static cudaEvent_t evA, evB, evC;
    static bool inited = false;
    if (!inited) {
        cudaStreamCreateWithFlags(&s1, cudaStreamNonBlocking);
        cudaEventCreateWithFlags(&evA, cudaEventDisableTiming);
        cudaEventCreateWithFlags(&evB, cudaEventDisableTiming);
        cudaEventCreateWithFlags(&evC, cudaEventDisableTiming);
        inited = true;
    }
    cudaStream_t s0 = (cudaStream_t)0;
    const int T = 256;

    // side stream: weight splits + CSR build
    cudaEventRecord(evA, s0);
    cudaStreamWaitEvent(s1, evA, 0);
    k_wconv<<<(NHF * FIN / 2 + T - 1) / T, T, 0, s1>>>(0, FIN, W[0]);
    k_wconv<<<(NHF * NHF / 2 + T - 1) / T, T, 0, s1>>>(1, NHF, W[1]);
    k_wconv<<<(NHF * NHF / 2 + T - 1) / T, T, 0, s1>>>(2, NHF, W[2]);
    cudaEventRecord(evC, s1);       // wconv(0) done before first xw (conservative: all three)
    k_bconv<<<(G4 * (D6 / 2)) / T, T, 0, s1>>>(Wih);
    k_p1conv<<<(256 * 1536) / T, T, 0, s1>>>(Wp1);
    k_prep<<<2 * NN / T, T, 0, s1>>>();
    k_count<<<dim3(NE / T, 2), T, 0, s1>>>(ei1, ea1, ei2, ea2);
    k_scan<<<2, 1024, 0, s1>>>();
    k_startsdinv<<<dim3(NN / T, 2), T, 0, s1>>>(b1, b2);
    k_fill<<<dim3(NE / T, 2), T, 0, s1>>>(ei1, ea1, ei2, ea2);
    cudaEventRecord(evB, s1);

    k_cvec<<<G4 / 8, T, 0, s0>>>(Wih, Whh, bih, bhh);
    cudaStreamWaitEvent(s0, evC, 0);    // W splits ready
    k_xw_mma<<<dim3(NN / 128, 2), T, 0, s0>>>(f1, f2, 0);

    cudaStreamWaitEvent(s0, evB, 0);    // CSR ready
    k_gather_t<false><<<dim3(NN / 8, 2), T, 0, s0>>>(0, bW[0]);
    k_xw_mma<<<dim3(NN / 128, 2), T, 0, s0>>>(f1, f2, 1);
    k_gather_t<false><<<dim3(NN / 8, 2), T, 0, s0>>>(NHF, bW[1]);
    k_xw_mma<<<dim3(NN / 128, 2), T, 0, s0>>>(f1, f2, 2);
    k_gather_t<true><<<dim3(NN / 8, 2), T, 0, s0>>>(2 * NHF, bW[2]);
    k_interact<<<NB, 512, 0, s0>>>();

    k_attn1<<<dim3(NB, 2), T, 0, s0>>>(bih, bhh);
    k_gates2_mma<<<dim3(G4 / 128, 2, 2), T, 0, s0>>>();
    k_attn2<<<dim3(NB, 2), T, 0, s0>>>(bih, bhh);

    k_mlp1_mma<<<dim3(2, 2, 12), T, 0, s0>>>();
    k_mlp2f<<<NB, T, 0, s0>>>(bp1, Wp2, bp2, Wp3, bp3, out);
}

// round 17
// speedup vs baseline: 1.2957x; 1.0288x over previous
#include <cuda_runtime.h>
#include <cuda_bf16.h>
#include <cstdint>

#define NN   8192
#define NE   131072
#define NB   256
#define NHF  128
#define FIN  64
#define H3   384
#define D6   768
#define D12  1536
#define G4   3072
#define SMAXSEG 512
#define KSPLIT 2304
#define KU    (KSPLIT / 2)
#define NCH   36

// ---------------- scratch ----------------
__device__ __align__(16) float g_h[2][NN * H3];
__device__ __align__(16) float g_x[2][NN * D6];
__device__ __align__(16) float g_xw[2][NN * NHF];
__device__ float g_deg[2][NN];
__device__ int   g_cnt[2][NN];
__device__ int   g_cursor[2][NN];
__device__ int   g_rowptr[2][NN + 1];
__device__ int   g_csrc[2][NE];
__device__ float g_cnrm[2][NE];
__device__ float g_dinv[2][NN];
__device__ int   g_starts[2][NB + 1];
__device__ float g_cvec[G4];
__device__ __align__(16) float g_rb[2][NB * D6];
__device__ __align__(16) float g_gates[2][NB * G4];
__device__ __align__(16) float g_z[NB * G4];
__device__ __align__(16) float g_z1pre[NB * 256];
__device__ __align__(16) uint32_t g_Bbuf[G4 * KU];
__device__ __align__(16) uint32_t g_Abuf[2][NB * KU];
__device__ __align__(16) uint32_t g_Wbuf[3][NHF * 192];
__device__ __align__(16) uint32_t g_P1buf[256 * 4608];

__device__ __forceinline__ float wredsum(float v) {
#pragma unroll
    for (int o = 16; o; o >>= 1) v += __shfl_xor_sync(0xffffffffu, v, o);
    return v;
}
__device__ __forceinline__ float sgm(float x) { return 1.f / (1.f + expf(-x)); }
__device__ __forceinline__ uint32_t bf16pack(float a, float b) {
    __nv_bfloat162 p; p.x = __float2bfloat16(a); p.y = __float2bfloat16(b);
    return *(uint32_t*)&p;
}
__device__ __forceinline__ uint32_t bf16lo(float a, float b) {
    __nv_bfloat16 h0 = __float2bfloat16(a);
    __nv_bfloat16 h1 = __float2bfloat16(b);
    return bf16pack(a - __bfloat162float(h0), b - __bfloat162float(h1));
}

// ---------------- CSR build (proven) ----------------
__global__ void k_prep() {
    int i = blockIdx.x * blockDim.x + threadIdx.x;
    if (i < 2 * NN) {
        int g = i >> 13, n = i & (NN - 1);
        g_cnt[g][n] = 0;
        g_deg[g][n] = 0.f;
    }
}
__global__ void k_count(const int* __restrict__ ei1, const float* __restrict__ ew1,
                        const int* __restrict__ ei2, const float* __restrict__ ew2) {
    int g = blockIdx.y;
    const int* ei = g ? ei2 : ei1;
    const float* ew = g ? ew2 : ew1;
    int e = blockIdx.x * blockDim.x + threadIdx.x;
    if (e < NE) {
        int d = ei[NE + e];
        atomicAdd(&g_cnt[g][d], 1);
        atomicAdd(&g_deg[g][d], ew[e]);
    }
}
__global__ void k_scan() {
    __shared__ int wsum[32];
    int g = blockIdx.x;
    int t = threadIdx.x, lane = t & 31, w = t >> 5;
    int base = t * 8;
    int loc[8], s = 0;
#pragma unroll
    for (int i = 0; i < 8; i++) { loc[i] = s; s += g_cnt[g][base + i]; }
    int x = s;
#pragma unroll
    for (int o = 1; o < 32; o <<= 1) {
        int y = __shfl_up_sync(0xffffffffu, x, o);
        if (lane >= o) x += y;
    }
    if (lane == 31) wsum[w] = x;
    __syncthreads();
    if (w == 0) {
        int y = wsum[lane];
#pragma unroll
        for (int o = 1; o < 32; o <<= 1) {
            int z = __shfl_up_sync(0xffffffffu, y, o);
            if (lane >= o) y += z;
        }
        wsum[lane] = y;
    }
    __syncthreads();
    int off = x - s + ((w > 0) ? wsum[w - 1] : 0);
#pragma unroll
    for (int i = 0; i < 8; i++) {
        g_rowptr[g][base + i] = off + loc[i];
        g_cursor[g][base + i] = off + loc[i];
    }
    if (t == 1023) g_rowptr[g][NN] = wsum[31];
}
__global__ void k_startsdinv(const int* __restrict__ b1, const int* __restrict__ b2) {
    int g = blockIdx.y;
    int n = blockIdx.x * blockDim.x + threadIdx.x;
    if (n >= NN) return;
    g_dinv[g][n] = rsqrtf(g_deg[g][n] + 1.0f);
    const int* batch = g ? b2 : b1;
    int b = batch[n];
    if (n == 0) {
        for (int bb = 0; bb <= b; bb++) g_starts[g][bb] = 0;
    } else {
        int pb = batch[n - 1];
        if (pb != b) for (int bb = pb + 1; bb <= b; bb++) g_starts[g][bb] = n;
    }
    if (n == NN - 1) for (int bb = b + 1; bb <= NB; bb++) g_starts[g][bb] = NN;
}
__global__ void k_fill(const int* __restrict__ ei1, const float* __restrict__ ew1,
                       const int* __restrict__ ei2, const float* __restrict__ ew2) {
    int g = blockIdx.y;
    const int* ei = g ? ei2 : ei1;
    const float* ew = g ? ew2 : ew1;
    int e = blockIdx.x * blockDim.x + threadIdx.x;
    if (e >= NE) return;
    int s = ei[e], d = ei[NE + e];
    int pos = atomicAdd(&g_cursor[g][d], 1);
    g_csrc[g][pos] = s;
    g_cnrm[g][pos] = g_dinv[g][s] * ew[e] * g_dinv[g][d];
}

// ---------------- operand pre-splits ----------------
__global__ void k_bconv(const float* __restrict__ Wih) {
    int i = blockIdx.x * blockDim.x + threadIdx.x;
    if (i >= G4 * (D6 / 2)) return;
    int n = i / (D6 / 2), p = i - n * (D6 / 2);
    const float* wr = Wih + (size_t)n * D12 + D6 + 2 * p;
    float v0 = wr[0], v1 = wr[1];
    uint32_t hu = bf16pack(v0, v1);
    uint32_t lu = bf16lo(v0, v1);
    uint32_t* row = g_Bbuf + (size_t)n * KU;
    row[p] = hu;
    row[(D6 / 2) + p] = hu;
    row[2 * (D6 / 2) + p] = lu;
}
__global__ void k_wconv(int l, int K, const float* __restrict__ W) {
    int i = blockIdx.x * blockDim.x + threadIdx.x;
    int half = K / 2;
    if (i >= NHF * half) return;
    int n = i / half, p = i - n * half;
    float v0 = W[(size_t)(2 * p) * NHF + n];
    float v1 = W[(size_t)(2 * p + 1) * NHF + n];
    uint32_t hu = bf16pack(v0, v1);
    uint32_t lu = bf16lo(v0, v1);
    uint32_t* row = g_Wbuf[l] + (size_t)n * 192;
    row[p] = hu;
    row[half + p] = hu;
    row[2 * half + p] = lu;
}
__global__ void k_p1conv(const float* __restrict__ Wp1) {
    int i = blockIdx.x * blockDim.x + threadIdx.x;
    if (i >= 256 * 1536) return;
    int o = i / 1536, p = i - o * 1536;
    const float* wr = Wp1 + (size_t)o * G4 + 2 * p;
    float v0 = wr[0], v1 = wr[1];
    uint32_t hu = bf16pack(v0, v1);
    uint32_t lu = bf16lo(v0, v1);
    uint32_t* row = g_P1buf + (size_t)o * 4608;
    row[p] = hu;
    row[1536 + p] = hu;
    row[3072 + p] = lu;
}

// ---------------- shared mma tile core (R15 proven) ----------------
struct MmaAcc { float c[4][4][4]; };
__device__ __forceinline__ void mma_chunk(uint32_t aBase, uint32_t bBase,
                                          int lane, int wm, int wn, MmaAcc& A) {
#pragma unroll
    for (int kf = 0; kf < 4; kf++) {
        uint32_t a[4][4];
#pragma unroll
        for (int mf = 0; mf < 4; mf++) {
            int row = wm * 64 + mf * 16 + (lane & 15);
            uint32_t addr = aBase + (row * 36 + kf * 8 + (lane >> 4) * 4) * 4;
            asm volatile("ldmatrix.sync.aligned.m8n8.x4.shared.b16 {%0,%1,%2,%3}, [%4];"
                         : "=r"(a[mf][0]), "=r"(a[mf][1]), "=r"(a[mf][2]), "=r"(a[mf][3])
                         : "r"(addr));
        }
#pragma unroll
        for (int nf = 0; nf < 4; nf++) {
            int nrow = wn * 32 + nf * 8 + (lane & 7);
            uint32_t addr = bBase + (nrow * 36 + kf * 8 + ((lane >> 3) & 1) * 4) * 4;
            uint32_t b0, b1;
            asm volatile("ldmatrix.sync.aligned.m8n8.x2.shared.b16 {%0,%1}, [%2];"
                         : "=r"(b0), "=r"(b1) : "r"(addr));
#pragma unroll
            for (int mf = 0; mf < 4; mf++) {
                asm volatile(
                    "mma.sync.aligned.m16n8k16.row.col.f32.bf16.bf16.f32 "
                    "{%0,%1,%2,%3}, {%4,%5,%6,%7}, {%8,%9}, {%0,%1,%2,%3};"
                    : "+f"(A.c[mf][nf][0]), "+f"(A.c[mf][nf][1]),
                      "+f"(A.c[mf][nf][2]), "+f"(A.c[mf][nf][3])
                    : "r"(a[mf][0]), "r"(a[mf][1]), "r"(a[mf][2]), "r"(a[mf][3]),
                      "r"(b0), "r"(b1));
            }
        }
    }
}

// ---------------- gates2 (R15 proven) ----------------
__global__ void __launch_bounds__(256) k_gates2_mma() {
    __shared__ __align__(16) uint32_t As[128][36];
    __shared__ __align__(16) uint32_t Bs[128][36];
    int tid = threadIdx.x, lane = tid & 31, wid = tid >> 5;
    int wm = wid >> 2, wn = wid & 3;
    int colBase = blockIdx.x * 128, rowBase = blockIdx.y * 128, g = blockIdx.z;
    const uint32_t* Abuf = g_Abuf[g];
    MmaAcc acc;
#pragma unroll
    for (int mf = 0; mf < 4; mf++)
#pragma unroll
        for (int nf = 0; nf < 4; nf++)
#pragma unroll
            for (int q = 0; q < 4; q++) acc.c[mf][nf][q] = 0.f;
    uint32_t aBase = (uint32_t)__cvta_generic_to_shared(&As[0][0]);
    uint32_t bBase = (uint32_t)__cvta_generic_to_shared(&Bs[0][0]);
    for (int ch = 0; ch < NCH; ch++) {
        __syncthreads();
#pragma unroll
        for (int l = 0; l < 4; l++) {
            int i = tid + l * 256;
            int m = i >> 3, p = i & 7;
            *(uint4*)&As[m][p * 4] = *(const uint4*)&Abuf[(size_t)(rowBase + m) * KU + ch * 32 + p * 4];
            *(uint4*)&Bs[m][p * 4] = *(const uint4*)&g_Bbuf[(size_t)(colBase + m) * KU + ch * 32 + p * 4];
        }
        __syncthreads();
        mma_chunk(aBase, bBase, lane, wm, wn, acc);
    }
    int rloc = lane >> 2, cloc = (lane & 3) * 2;
#pragma unroll
    for (int mf = 0; mf < 4; mf++) {
#pragma unroll
        for (int nf = 0; nf < 4; nf++) {
            int row = rowBase + wm * 64 + mf * 16 + rloc;
            int col = colBase + wn * 32 + nf * 8 + cloc;
            float* dst = g_gates[g] + (size_t)row * G4 + col;
            dst[0] = acc.c[mf][nf][0] + g_cvec[col];
            dst[1] = acc.c[mf][nf][1] + g_cvec[col + 1];
            float* dst2 = dst + 8 * G4;
            dst2[0] = acc.c[mf][nf][2] + g_cvec[col];
            dst2[1] = acc.c[mf][nf][3] + g_cvec[col + 1];
        }
    }
}

// ---------------- xw via mma (R16 proven) ----------------
__global__ void __launch_bounds__(256) k_xw_mma(const float* __restrict__ f1,
                                                const float* __restrict__ f2,
                                                int layer) {
    __shared__ __align__(16) uint32_t As[128][36];
    __shared__ __align__(16) uint32_t Bs[128][36];
    int tid = threadIdx.x, lane = tid & 31, wid = tid >> 5;
    int wm = wid >> 2, wn = wid & 3;
    int rowBase = blockIdx.x * 128, g = blockIdx.y;
    const float* X;
    int ldx, K;
    if (layer == 0) { X = g ? f2 : f1; ldx = FIN; K = FIN; }
    else            { X = g_h[g] + (layer - 1) * NHF; ldx = H3; K = NHF; }
    int segch = K / 64;
    int nch = 3 * segch;
    const uint32_t* Wb = g_Wbuf[layer];
    MmaAcc acc;
#pragma unroll
    for (int mf = 0; mf < 4; mf++)
#pragma unroll
        for (int nf = 0; nf < 4; nf++)
#pragma unroll
            for (int q = 0; q < 4; q++) acc.c[mf][nf][q] = 0.f;
    uint32_t aBase = (uint32_t)__cvta_generic_to_shared(&As[0][0]);
    uint32_t bBase = (uint32_t)__cvta_generic_to_shared(&Bs[0][0]);
    for (int ch = 0; ch < nch; ch++) {
        int seg = ch / segch;
        int koff = (ch - seg * segch) * 64;
        __syncthreads();
#pragma unroll
        for (int l = 0; l < 4; l++) {
            int i = tid + l * 256;
            int m = i >> 3, p = i & 7;
            const float* src = X + (size_t)(rowBase + m) * ldx + koff + p * 8;
            float4 f0 = *(const float4*)src;
            float4 f1v = *(const float4*)(src + 4);
            uint4 o;
            if (seg == 1) {
                o.x = bf16lo(f0.x, f0.y); o.y = bf16lo(f0.z, f0.w);
                o.z = bf16lo(f1v.x, f1v.y); o.w = bf16lo(f1v.z, f1v.w);
            } else {
                o.x = bf16pack(f0.x, f0.y); o.y = bf16pack(f0.z, f0.w);
                o.z = bf16pack(f1v.x, f1v.y); o.w = bf16pack(f1v.z, f1v.w);
            }
            *(uint4*)&As[m][p * 4] = o;
            *(uint4*)&Bs[m][p * 4] = *(const uint4*)&Wb[(size_t)m * 192 + ch * 32 + p * 4];
        }
        __syncthreads();
        mma_chunk(aBase, bBase, lane, wm, wn, acc);
    }
    int rloc = lane >> 2, cloc = (lane & 3) * 2;
#pragma unroll
    for (int mf = 0; mf < 4; mf++) {
#pragma unroll
        for (int nf = 0; nf < 4; nf++) {
            int row = rowBase + wm * 64 + mf * 16 + rloc;
            int col = wn * 32 + nf * 8 + cloc;
            float* dst = g_xw[g] + (size_t)row * NHF + col;
            dst[0] = acc.c[mf][nf][0];
            dst[1] = acc.c[mf][nf][1];
            float* dst2 = dst + 8 * NHF;
            dst2[0] = acc.c[mf][nf][2];
            dst2[1] = acc.c[mf][nf][3];
        }
    }
}

// ---------------- mlp1 via mma (R16 proven) ----------------
__global__ void __launch_bounds__(256) k_mlp1_mma() {
    __shared__ __align__(16) uint32_t As[128][36];
    __shared__ __align__(16) uint32_t Bs[128][36];
    int tid = threadIdx.x, lane = tid & 31, wid = tid >> 5;
    int wm = wid >> 2, wn = wid & 3;
    int colBase = blockIdx.x * 128, rowBase = blockIdx.y * 128;
    MmaAcc acc;
#pragma unroll
    for (int mf = 0; mf < 4; mf++)
#pragma unroll
        for (int nf = 0; nf < 4; nf++)
#pragma unroll
            for (int q = 0; q < 4; q++) acc.c[mf][nf][q] = 0.f;
    uint32_t aBase = (uint32_t)__cvta_generic_to_shared(&As[0][0]);
    uint32_t bBase = (uint32_t)__cvta_generic_to_shared(&Bs[0][0]);
    for (int ci = 0; ci < 12; ci++) {
        int ch = blockIdx.z * 12 + ci;
        int seg = ch / 48;
        int koff = (ch - seg * 48) * 64;
        __syncthreads();
#pragma unroll
        for (int l = 0; l < 4; l++) {
            int i = tid + l * 256;
            int m = i >> 3, p = i & 7;
            const float* src = g_z + (size_t)(rowBase + m) * G4 + koff + p * 8;
            float4 f0 = *(const float4*)src;
            float4 f1v = *(const float4*)(src + 4);
            uint4 o;
            if (seg == 1) {
                o.x = bf16lo(f0.x, f0.y); o.y = bf16lo(f0.z, f0.w);
                o.z = bf16lo(f1v.x, f1v.y); o.w = bf16lo(f1v.z, f1v.w);
            } else {
                o.x = bf16pack(f0.x, f0.y); o.y = bf16pack(f0.z, f0.w);
                o.z = bf16pack(f1v.x, f1v.y); o.w = bf16pack(f1v.z, f1v.w);
            }
            *(uint4*)&As[m][p * 4] = o;
            *(uint4*)&Bs[m][p * 4] = *(const uint4*)&g_P1buf[(size_t)(colBase + m) * 4608 + ch * 32 + p * 4];
        }
        __syncthreads();
        mma_chunk(aBase, bBase, lane, wm, wn, acc);
    }
    int rloc = lane >> 2, cloc = (lane & 3) * 2;
#pragma unroll
    for (int mf = 0; mf < 4; mf++) {
#pragma unroll
        for (int nf = 0; nf < 4; nf++) {
            int row = rowBase + wm * 64 + mf * 16 + rloc;
            int col = colBase + wn * 32 + nf * 8 + cloc;
            float* dst = g_z1pre + (size_t)row * 256 + col;
            atomicAdd(&dst[0], acc.c[mf][nf][0]);
            atomicAdd(&dst[1], acc.c[mf][nf][1]);
            float* dst2 = dst + 8 * 256;
            atomicAdd(&dst2[0], acc.c[mf][nf][2]);
            atomicAdd(&dst2[1], acc.c[mf][nf][3]);
        }
    }
}

// ---------------- gather (R8 proven; L2 norm fused on last layer) ----------------
template<bool FUSE_L2>
__global__ void k_gather_t(int off, const float* __restrict__ bias) {
    int g = blockIdx.y;
    int n = blockIdx.x * 8 + (threadIdx.x >> 5);
    int lane = threadIdx.x & 31;
    if (n >= NN) return;
    const float4* xw4 = (const float4*)g_xw[g];
    float di = g_dinv[g][n];
    float sn = di * di;
    float4 bb = ((const float4*)bias)[lane];
    float4 sv = xw4[(size_t)n * 32 + lane];
    float ax = bb.x + sn * sv.x, ay = bb.y + sn * sv.y;
    float az = bb.z + sn * sv.z, aw = bb.w + sn * sv.w;
    int e0 = g_rowptr[g][n], e1 = g_rowptr[g][n + 1];
    const int* __restrict__ csrc = g_csrc[g];
    const float* __restrict__ cnrm = g_cnrm[g];
    for (int e = e0; e < e1; e++) {
        int s = csrc[e];
        float nm = cnrm[e];
        float4 v = xw4[(size_t)s * 32 + lane];
        ax += nm * v.x; ay += nm * v.y; az += nm * v.z; aw += nm * v.w;
    }
    ax = (ax >= 0.f) ? ax : 0.2f * ax;
    ay = (ay >= 0.f) ? ay : 0.2f * ay;
    az = (az >= 0.f) ? az : 0.2f * az;
    aw = (aw >= 0.f) ? aw : 0.2f * aw;
    if (!FUSE_L2) {
        float4* o = (float4*)(g_h[g] + (size_t)n * H3 + off);
        o[lane] = make_float4(ax, ay, az, aw);
    } else {
        const float4* hrow = (const float4*)(g_h[g] + (size_t)n * H3);
        float4 v0 = hrow[lane];
        float4 v1 = hrow[lane + 32];
        float ss = v0.x * v0.x + v0.y * v0.y + v0.z * v0.z + v0.w * v0.w
                 + v1.x * v1.x + v1.y * v1.y + v1.z * v1.z + v1.w * v1.w
                 + ax * ax + ay * ay + az * az + aw * aw;
        ss = wredsum(ss);
        float inv = 1.f / fmaxf(sqrtf(ss), 1e-12f);
        float4* xr = (float4*)(g_x[g] + (size_t)n * D6);
        xr[lane]      = make_float4(v0.x * inv, v0.y * inv, v0.z * inv, v0.w * inv);
        xr[lane + 32] = make_float4(v1.x * inv, v1.y * inv, v1.z * inv, v1.w * inv);
        xr[lane + 64] = make_float4(ax * inv, ay * inv, az * inv, aw * inv);
    }
}

// ---------------- interaction: direction-split (R11-proven variant), grid (NB, 2) ----------------
__global__ void __launch_bounds__(256) k_interact() {
    int b = blockIdx.x;
    int dir = blockIdx.y;              // 0: graph-0 targets ; 1: graph-1 targets
    int s1 = g_starts[0][b], e1 = g_starts[0][b + 1];
    int s2 = g_starts[1][b], e2 = g_starts[1][b + 1];
    int sA = dir ? s2 : s1, nA = dir ? (e2 - s2) : (e1 - s1);
    int sB = dir ? s1 : s2, nB = dir ? (e1 - s1) : (e2 - s2);
    const float* srcb = g_x[dir];
    const float* oth = g_x[dir ^ 1];
    float* outb = g_x[dir];
    int lane = threadIdx.x & 31, w = threadIdx.x >> 5;
    for (int t = w; t < nA; t += 8) {
        int row = sA + t;
        const float* sr = srcb + (size_t)row * D6;
        float sv[12], acc[12];
#pragma unroll
        for (int q = 0; q < 12; q++) { sv[q] = sr[lane + 32 * q]; acc[q] = 0.f; }
        for (int jj = 0; jj < nB; jj++) {
            const float* vr = oth + (size_t)(sB + jj) * D6;
            float vv[12], p = 0.f;
#pragma unroll
            for (int q = 0; q < 12; q++) { vv[q] = vr[lane + 32 * q]; p += sv[q] * vv[q]; }
            p = wredsum(p);
#pragma unroll
            for (int q = 0; q < 12; q++) acc[q] += p * vv[q];
        }
        float* orow = outb + (size_t)row * D6 + H3;
#pragma unroll
        for (int q = 0; q < 12; q++) orow[lane + 32 * q] = acc[q];
    }
}

// ---------------- cvec + z1pre zero (side stream) ----------------
__global__ void k_cvec(const float* __restrict__ Wih, const float* __restrict__ Whh,
                       const float* __restrict__ bih, const float* __restrict__ bhh) {
    __shared__ float shv[D6];
    int tid = threadIdx.x, lane = tid & 31, w = tid >> 5;
    for (int j = tid; j < D6; j += 256) {
        float gi = bih[j] + bhh[j];
        float gg = bih[2 * D6 + j] + bhh[2 * D6 + j];
        float go = bih[3 * D6 + j] + bhh[3 * D6 + j];
        float c = sgm(gi) * tanhf(gg);
        shv[j] = sgm(go) * tanhf(c);
    }
    if (blockIdx.x < 256) g_z1pre[blockIdx.x * 256 + tid] = 0.f;
    __syncthreads();
    int gout = blockIdx.x * 8 + w;
    const float* wi = Wih + (size_t)gout * D12;
    const float* wh = Whh + (size_t)gout * D6;
    float p = 0.f;
#pragma unroll
    for (int t = 0; t < 24; t++) {
        int k = lane + 32 * t;
        p += shv[k] * (wi[k] + wh[k]);
    }
    p = wredsum(p);
    if (lane == 0) g_cvec[gout] = bih[gout] + bhh[gout] + p;
}

// ---------------- attn step 1 (R15 proven, with A' epilogue) ----------------
__global__ void k_attn1(const float* __restrict__ bih, const float* __restrict__ bhh) {
    __shared__ float hq[D6];
    __shared__ float sc[SMAXSEG];
    __shared__ float red[256];
    int g = blockIdx.y, b = blockIdx.x;
    int tid = threadIdx.x, lane = tid & 31, w = tid >> 5;
    uint32_t* arow = g_Abuf[g] + (size_t)b * KU;
    for (int j = tid; j < D6; j += 256) {
        float gi = bih[j] + bhh[j];
        float gg = bih[2 * D6 + j] + bhh[2 * D6 + j];
        float go = bih[3 * D6 + j] + bhh[3 * D6 + j];
        float c = sgm(gi) * tanhf(gg);
        hq[j] = sgm(go) * tanhf(c);
    }
    __syncthreads();
    int s = g_starts[g][b], e = g_starts[g][b + 1], cnt = e - s;
    float* rout = g_rb[g] + (size_t)b * D6;
    if (cnt <= 0) {
        for (int j = tid; j < D6; j += 256) rout[j] = 0.f;
        for (int j = tid; j < KU; j += 256) arow[j] = 0u;
        return;
    }
    const float* x = g_x[g];
    for (int t = w; t < cnt; t += 8) {
        const float* xr = x + (size_t)(s + t) * D6;
        float p = 0.f;
#pragma unroll
        for (int q = 0; q < 24; q++) p += xr[lane + 32 * q] * hq[lane + 32 * q];
        p = wredsum(p);
        if (lane == 0) sc[t] = p;
    }
    __syncthreads();
    float lm = -3.4e38f;
    for (int t = tid; t < cnt; t += 256) lm = fmaxf(lm, sc[t]);
    red[tid] = lm; __syncthreads();
    for (int o = 128; o > 0; o >>= 1) { if (tid < o) red[tid] = fmaxf(red[tid], red[tid + o]); __syncthreads(); }
    float m = red[0]; __syncthreads();
    float ls = 0.f;
    for (int t = tid; t < cnt; t += 256) { float ev = expf(sc[t] - m); sc[t] = ev; ls += ev; }
    red[tid] = ls; __syncthreads();
    for (int o = 128; o > 0; o >>= 1) { if (tid < o) red[tid] += red[tid + o]; __syncthreads(); }
    float S = red[0]; __syncthreads();
    float a0 = 0.f, a1 = 0.f, a2 = 0.f;
    for (int t = 0; t < cnt; t++) {
        float wv = sc[t];
        const float* xr = x + (size_t)(s + t) * D6;
        a0 += wv * xr[tid];
        a1 += wv * xr[tid + 256];
        a2 += wv * xr[tid + 512];
    }
    float inv = 1.f / S;
    rout[tid] = a0 * inv;
    rout[tid + 256] = a1 * inv;
    rout[tid + 512] = a2 * inv;
    __syncthreads();
    for (int p = tid; p < D6 / 2; p += 256) {
        float v0 = rout[2 * p], v1 = rout[2 * p + 1];
        uint32_t hu = bf16pack(v0, v1);
        uint32_t lu = bf16lo(v0, v1);
        arow[p] = hu;
        arow[(D6 / 2) + p] = lu;
        arow[2 * (D6 / 2) + p] = hu;
    }
}

// ---------------- attn step 2 (R8 proven) ----------------
__global__ void k_attn2(const float* __restrict__ bih, const float* __restrict__ bhh) {
    __shared__ float hq[D6];
    __shared__ float sc[SMAXSEG];
    __shared__ float red[256];
    int g = blockIdx.y, b = blockIdx.x;
    int tid = threadIdx.x, lane = tid & 31, w = tid >> 5;
    const float* gt = g_gates[g] + (size_t)b * G4;
    float* zb = g_z + (size_t)b * G4 + (g ? D12 : 0);
    for (int j = tid; j < D6; j += 256) {
        float gi1 = bih[j] + bhh[j];
        float gg1 = bih[2 * D6 + j] + bhh[2 * D6 + j];
        float cv = sgm(gi1) * tanhf(gg1);
        float gi = gt[j], gf = gt[D6 + j], gg = gt[2 * D6 + j], go = gt[3 * D6 + j];
        float c = sgm(gf) * cv + sgm(gi) * tanhf(gg);
        float h = sgm(go) * tanhf(c);
        hq[j] = h;
        zb[j] = h;
    }
    __syncthreads();
    int s = g_starts[g][b], e = g_starts[g][b + 1], cnt = e - s;
    float* rout = zb + D6;
    if (cnt <= 0) {
        for (int j = tid; j < D6; j += 256) rout[j] = 0.f;
        return;
    }
    const float* x = g_x[g];
    for (int t = w; t < cnt; t += 8) {
        const float* xr = x + (size_t)(s + t) * D6;
        float p = 0.f;
#pragma unroll
        for (int q = 0; q < 24; q++) p += xr[lane + 32 * q] * hq[lane + 32 * q];
        p = wredsum(p);
        if (lane == 0) sc[t] = p;
    }
    __syncthreads();
    float lm = -3.4e38f;
    for (int t = tid; t < cnt; t += 256) lm = fmaxf(lm, sc[t]);
    red[tid] = lm; __syncthreads();
    for (int o = 128; o > 0; o >>= 1) { if (tid < o) red[tid] = fmaxf(red[tid], red[tid + o]); __syncthreads(); }
    float m = red[0]; __syncthreads();
    float ls = 0.f;
    for (int t = tid; t < cnt; t += 256) { float ev = expf(sc[t] - m); sc[t] = ev; ls += ev; }
    red[tid] = ls; __syncthreads();
    for (int o = 128; o > 0; o >>= 1) { if (tid < o) red[tid] += red[tid + o]; __syncthreads(); }
    float S = red[0]; __syncthreads();
    float a0 = 0.f, a1 = 0.f, a2 = 0.f;
    for (int t = 0; t < cnt; t++) {
        float wv = sc[t];
        const float* xr = x + (size_t)(s + t) * D6;
        a0 += wv * xr[tid];
        a1 += wv * xr[tid + 256];
        a2 += wv * xr[tid + 512];
    }
    float inv = 1.f / S;
    rout[tid] = a0 * inv;
    rout[tid + 256] = a1 * inv;
    rout[tid + 512] = a2 * inv;
}

// ---------------- MLP tail (proven) ----------------
__global__ void k_mlp2f(const float* __restrict__ bp1,
                        const float* __restrict__ Wp2, const float* __restrict__ bp2,
                        const float* __restrict__ Wp3, const float* __restrict__ bp3,
                        float* __restrict__ out) {
    __shared__ float zs[256];
    __shared__ float z2s[128];
    int b = blockIdx.x, tid = threadIdx.x, lane = tid & 31, w = tid >> 5;
    zs[tid] = fmaxf(g_z1pre[(size_t)b * 256 + tid] + bp1[tid], 0.f);
    __syncthreads();
#pragma unroll
    for (int oo = 0; oo < 16; oo++) {
        int o = w * 16 + oo;
        const float* wr = Wp2 + (size_t)o * 256;
        float p = 0.f;
#pragma unroll
        for (int k = 0; k < 8; k++) p += zs[lane + 32 * k] * wr[lane + 32 * k];
        p = wredsum(p);
        if (lane == 0) z2s[o] = fmaxf(p + bp2[o], 0.f);
    }
    __syncthreads();
    if (w == 0) {
        float p = 0.f;
#pragma unroll
        for (int k = 0; k < 4; k++) p += z2s[lane + 32 * k] * Wp3[lane + 32 * k];
        p = wredsum(p);
        if (lane == 0) out[b] = 1.f / (1.f + expf(-p - bp3[0]));
    }
}

// ---------------- launch sequence ----------------
extern "C" void kernel_launch(void* const* d_in, const int* in_sizes, int n_in,
                              void* d_out, int out_size) {
    const float* f1 = (const float*)d_in[0];
    const float* f2 = (const float*)d_in[1];
    const float* ea1 = (const float*)d_in[2];
    const float* ea2 = (const float*)d_in[3];
    const float* W[3]  = { (const float*)d_in[4], (const float*)d_in[6], (const float*)d_in[8] };
    const float* bW[3] = { (const float*)d_in[5], (const float*)d_in[7], (const float*)d_in[9] };
    const float* Wih = (const float*)d_in[10];
    const float* bih = (const float*)d_in[11];
    const float* Whh = (const float*)d_in[12];
    const float* bhh = (const float*)d_in[13];
    const float* Wp1 = (const float*)d_in[14];
    const float* bp1 = (const float*)d_in[15];
    const float* Wp2 = (const float*)d_in[16];
    const float* bp2 = (const float*)d_in[17];
    const float* Wp3 = (const float*)d_in[18];
    const float* bp3 = (const float*)d_in[19];
    const int* ei1 = (const int*)d_in[20];
    const int* ei2 = (const int*)d_in[21];
    const int* b1 = (const int*)d_in[22];
    const int* b2 = (const int*)d_in[23];
    float* out = (float*)d_out;

    static cudaStream_t s1 = (cudaStream_t)0;
    static cudaEvent_t evA, evB, evC, evD;
    static bool inited = false;
    if (!inited) {
        cudaStreamCreateWithFlags(&s1, cudaStreamNonBlocking);
        cudaEventCreateWithFlags(&evA, cudaEventDisableTiming);
        cudaEventCreateWithFlags(&evB, cudaEventDisableTiming);
        cudaEventCreateWithFlags(&evC, cudaEventDisableTiming);
        cudaEventCreateWithFlags(&evD, cudaEventDisableTiming);
        inited = true;
    }
    cudaStream_t s0 = (cudaStream_t)0;
    const int T = 256;

    // side stream, ordered by consumer deadline:
    // 1) wconv (xw0 needs it immediately)  2) CSR (gather0)  3) cvec/bconv/p1conv (late consumers)
    cudaEventRecord(evA, s0);
    cudaStreamWaitEvent(s1, evA, 0);
    k_wconv<<<(NHF * FIN / 2 + T - 1) / T, T, 0, s1>>>(0, FIN, W[0]);
    k_wconv<<<(NHF * NHF / 2 + T - 1) / T, T, 0, s1>>>(1, NHF, W[1]);
    k_wconv<<<(NHF * NHF / 2 + T - 1) / T, T, 0, s1>>>(2, NHF, W[2]);
    cudaEventRecord(evC, s1);
    k_prep<<<2 * NN / T, T, 0, s1>>>();
    k_count<<<dim3(NE / T, 2), T, 0, s1>>>(ei1, ea1, ei2, ea2);
    k_scan<<<2, 1024, 0, s1>>>();
    k_startsdinv<<<dim3(NN / T, 2), T, 0, s1>>>(b1, b2);
    k_fill<<<dim3(NE / T, 2), T, 0, s1>>>(ei1, ea1, ei2, ea2);
    cudaEventRecord(evB, s1);
    k_cvec<<<G4 / 8, T, 0, s1>>>(Wih, Whh, bih, bhh);
    k_bconv<<<(G4 * (D6 / 2)) / T, T, 0, s1>>>(Wih);
    k_p1conv<<<(256 * 1536) / T, T, 0, s1>>>(Wp1);
    cudaEventRecord(evD, s1);

    cudaStreamWaitEvent(s0, evC, 0);    // W splits ready
    k_xw_mma<<<dim3(NN / 128, 2), T, 0, s0>>>(f1, f2, 0);
    cudaStreamWaitEvent(s0, evB, 0);    // CSR ready
    k_gather_t<false><<<dim3(NN / 8, 2), T, 0, s0>>>(0, bW[0]);
    k_xw_mma<<<dim3(NN / 128, 2), T, 0, s0>>>(f1, f2, 1);
    k_gather_t<false><<<dim3(NN / 8, 2), T, 0, s0>>>(NHF, bW[1]);
    k_xw_mma<<<dim3(NN / 128, 2), T, 0, s0>>>(f1, f2, 2);
    k_gather_t<true><<<dim3(NN / 8, 2), T, 0, s0>>>(2 * NHF, bW[2]);
    k_interact<<<dim3(NB, 2), T, 0, s0>>>();

    k_attn1<<<dim3(NB, 2), T, 0, s0>>>(bih, bhh);
    cudaStreamWaitEvent(s0, evD, 0);    // cvec + bconv + p1conv ready
    k_gates2_mma<<<dim3(G4 / 128, 2, 2), T, 0, s0>>>();
    k_attn2<<<dim3(NB, 2), T, 0, s0>>>(bih, bhh);

    k_mlp1_mma<<<dim3(2, 2, 12), T, 0, s0>>>();
    k_mlp2f<<<NB, T, 0, s0>>>(bp1, Wp2, bp2, Wp3, bp3, out);
}